// round 5
// baseline (speedup 1.0000x reference)
#include <cuda_runtime.h>
#include <cuda_bf16.h>

// ---------------- problem constants ----------------
#define BATCH 32
#define DIM   7168
#define H     128
#define QLR   1536
#define KVLR  512
#define DN    128
#define DR    64
#define DV    128
#define QKD   192
#define MAXS  4096
#define QDIM  (H*QKD)      // 24576
#define KCAT  (KVLR+DR)    // 576
#define ODIM  (H*DV)       // 16384

#define NSPLIT 4
#define TSPAN  (MAXS/NSPLIT)   // 1024
#define TT     256

#define SCALE_F 0.07216878364870322f
#define EPS_F   1e-6f

typedef unsigned long long ull;

// ---------------- helpers ----------------
__device__ __forceinline__ ull fma2(ull a, ull b, ull c) {
    ull d;
    asm("fma.rn.f32x2 %0, %1, %2, %3;" : "=l"(d) : "l"(a), "l"(b), "l"(c));
    return d;
}
__device__ __forceinline__ ull dup2(float x) {
    ull d;
    asm("mov.b64 %0, {%1, %1};" : "=l"(d) : "f"(x));
    return d;
}
__device__ __forceinline__ float2 u2f(ull v) {
    float2 f;
    f.x = __uint_as_float((unsigned)(v & 0xffffffffull));
    f.y = __uint_as_float((unsigned)(v >> 32));
    return f;
}
__device__ __forceinline__ unsigned f2tf(float f) {
    unsigned u; asm("cvt.rna.tf32.f32 %0, %1;" : "=r"(u) : "f"(f)); return u;
}
__device__ __forceinline__ void mma8(float* c, const unsigned* a, const unsigned* b) {
    asm volatile("mma.sync.aligned.m16n8k8.row.col.f32.tf32.tf32.f32 "
                 "{%0,%1,%2,%3}, {%4,%5,%6,%7}, {%8,%9}, {%0,%1,%2,%3};"
                 : "+f"(c[0]), "+f"(c[1]), "+f"(c[2]), "+f"(c[3])
                 : "r"(a[0]), "r"(a[1]), "r"(a[2]), "r"(a[3]),
                   "r"(b[0]), "r"(b[1]));
}

// ---------------- scratch ----------------
__device__ __align__(16) float g_qlat  [BATCH * QLR];
__device__ __align__(16) float g_kvfull[BATCH * KCAT];
__device__ __align__(16) float g_kvnew [BATCH * KVLR];
__device__ __align__(16) float g_penew [BATCH * DR];
__device__ __align__(16) float g_q     [BATCH * QDIM];
__device__ __align__(16) float g_qcat  [BATCH * H * KCAT];
__device__ __align__(16) float g_opart [(long long)NSPLIT * BATCH * H * KVLR];
__device__ __align__(16) float g_ml    [NSPLIT * BATCH * H * 2];
__device__ __align__(16) float g_olat  [BATCH * H * KVLR];
__device__ __align__(16) float g_ohead [BATCH * ODIM];

// ---------------- reductions ----------------
__device__ __forceinline__ float warpSum(float v) {
#pragma unroll
    for (int o = 16; o; o >>= 1) v += __shfl_xor_sync(0xffffffffu, v, o);
    return v;
}
__device__ __forceinline__ float blockSum256(float v) {
    __shared__ float sm[8];
    int lane = threadIdx.x & 31, w = threadIdx.x >> 5;
    __syncthreads();
    v = warpSum(v);
    if (!lane) sm[w] = v;
    __syncthreads();
    float r = 0.f;
#pragma unroll
    for (int i = 0; i < 8; i++) r += sm[i];
    return r;
}

// =====================================================================
// TF32 MMA split-K GEMV (unchanged from round 4)
// =====================================================================
__global__ void __launch_bounds__(256) gemv_mma(
    const float* __restrict__ A, const float* __restrict__ B, float* __restrict__ C,
    int lda, int ldb, int ldc, int kChunk)
{
    const int n0 = blockIdx.x * 256;
    const int ks = blockIdx.y * kChunk;
    const int ke = ks + kChunk;

    __shared__ unsigned As[16][40];
    __shared__ unsigned Bs[16][264];

    const int tid = threadIdx.x, lane = tid & 31, wid = tid >> 5;
    const int gid = lane >> 2, tig = lane & 3;
    const int wn = wid * 32;

    const bool aon = tid < 128;
    const int am = tid >> 2, akq = (tid & 3) * 4;
    const int aq = (akq >> 2) & 3;
    const long long brow = (long long)(n0 + tid) * ldb;

    float4 ra = make_float4(0,0,0,0);
    float4 rb[4];

    if (aon) ra = *(const float4*)(A + (long long)am * lda + ks + akq);
#pragma unroll
    for (int j = 0; j < 4; j++) rb[j] = *(const float4*)(B + brow + ks + j*4);

    if (aon) {
        int col = am ^ (8*aq);
        As[akq+0][col] = f2tf(ra.x); As[akq+1][col] = f2tf(ra.y);
        As[akq+2][col] = f2tf(ra.z); As[akq+3][col] = f2tf(ra.w);
    }
#pragma unroll
    for (int j = 0; j < 4; j++) {
        Bs[j*4+0][tid] = f2tf(rb[j].x); Bs[j*4+1][tid] = f2tf(rb[j].y);
        Bs[j*4+2][tid] = f2tf(rb[j].z); Bs[j*4+3][tid] = f2tf(rb[j].w);
    }
    __syncthreads();

    float acc[2][4][4];
#pragma unroll
    for (int mi = 0; mi < 2; mi++)
#pragma unroll
        for (int nj = 0; nj < 4; nj++)
#pragma unroll
            for (int r = 0; r < 4; r++) acc[mi][nj][r] = 0.f;

    for (int k0 = ks; k0 < ke; k0 += 16) {
        const bool more = (k0 + 16) < ke;
        if (more) {
            if (aon) ra = *(const float4*)(A + (long long)am * lda + (k0+16) + akq);
#pragma unroll
            for (int j = 0; j < 4; j++) rb[j] = *(const float4*)(B + brow + (k0+16) + j*4);
        }
#pragma unroll
        for (int s = 0; s < 2; s++) {
            const int kk = s * 8;
            const int key0 = 8 * ((kk >> 2) & 3);
            const int key1 = 8 * (((kk >> 2) + 1) & 3);
            unsigned af[2][4];
#pragma unroll
            for (int mi = 0; mi < 2; mi++) {
                int r0 = mi*16 + gid;
                af[mi][0] = As[kk+tig  ][ r0    ^ key0];
                af[mi][1] = As[kk+tig  ][(r0+8) ^ key0];
                af[mi][2] = As[kk+tig+4][ r0    ^ key1];
                af[mi][3] = As[kk+tig+4][(r0+8) ^ key1];
            }
            unsigned bf[4][2];
#pragma unroll
            for (int nj = 0; nj < 4; nj++) {
                bf[nj][0] = Bs[kk+tig  ][wn + nj*8 + gid];
                bf[nj][1] = Bs[kk+tig+4][wn + nj*8 + gid];
            }
#pragma unroll
            for (int mi = 0; mi < 2; mi++)
#pragma unroll
                for (int nj = 0; nj < 4; nj++)
                    mma8(acc[mi][nj], af[mi], bf[nj]);
        }
        __syncthreads();
        if (more) {
            if (aon) {
                int col = am ^ (8*aq);
                As[akq+0][col] = f2tf(ra.x); As[akq+1][col] = f2tf(ra.y);
                As[akq+2][col] = f2tf(ra.z); As[akq+3][col] = f2tf(ra.w);
            }
#pragma unroll
            for (int j = 0; j < 4; j++) {
                Bs[j*4+0][tid] = f2tf(rb[j].x); Bs[j*4+1][tid] = f2tf(rb[j].y);
                Bs[j*4+2][tid] = f2tf(rb[j].z); Bs[j*4+3][tid] = f2tf(rb[j].w);
            }
        }
        __syncthreads();
    }

#pragma unroll
    for (int mi = 0; mi < 2; mi++)
#pragma unroll
        for (int nj = 0; nj < 4; nj++) {
            float* cp = C + (long long)(mi*16+gid)*ldc + n0 + wn + nj*8 + 2*tig;
            atomicAdd(cp,           acc[mi][nj][0]);
            atomicAdd(cp + 1,       acc[mi][nj][1]);
            atomicAdd(cp + 8*ldc,   acc[mi][nj][2]);
            atomicAdd(cp + 8*ldc+1, acc[mi][nj][3]);
        }
}

// ---------------- rmsnorm (in place) ----------------
__global__ void __launch_bounds__(256) rmsnorm_kernel(float* __restrict__ v,
                                                      const float* __restrict__ w, int n)
{
    int b = blockIdx.x;
    float* row = v + (long long)b * n;
    float ss = 0.f;
    for (int i = threadIdx.x; i < n; i += 256) { float x = row[i]; ss += x * x; }
    ss = blockSum256(ss);
    __shared__ float s_scale;
    if (threadIdx.x == 0) s_scale = rsqrtf(ss / (float)n + EPS_F);
    __syncthreads();
    float sc = s_scale;
    for (int i = threadIdx.x; i < n; i += 256) row[i] = row[i] * sc * w[i];
}

// ---------------- kv prep ----------------
__global__ void __launch_bounds__(256) kvprep_kernel(
    const float* __restrict__ kvfull, const float* __restrict__ w,
    const float* __restrict__ fc, const float* __restrict__ fs,
    float* __restrict__ kvnew, float* __restrict__ penew)
{
    int b = blockIdx.x;
    const float* row = kvfull + (long long)b * KCAT;
    float ss = 0.f;
    for (int i = threadIdx.x; i < KVLR; i += 256) { float x = row[i]; ss += x * x; }
    ss = blockSum256(ss);
    __shared__ float s_scale;
    if (threadIdx.x == 0) s_scale = rsqrtf(ss / (float)KVLR + EPS_F);
    __syncthreads();
    float sc = s_scale;
    for (int i = threadIdx.x; i < KVLR; i += 256)
        kvnew[(long long)b * KVLR + i] = row[i] * sc * w[i];
    if (threadIdx.x < 32) {
        int i = threadIdx.x;
        float x1 = row[KVLR + 2 * i], x2 = row[KVLR + 2 * i + 1];
        float c = fc[i], s = fs[i];
        penew[(long long)b * DR + 2 * i]     = x1 * c - x2 * s;
        penew[(long long)b * DR + 2 * i + 1] = x1 * s + x2 * c;
    }
}

// ---------------- q rope -> qcat tail (scaled) ----------------
__global__ void __launch_bounds__(256) qrope_kernel(
    const float* __restrict__ q, const float* __restrict__ fc,
    const float* __restrict__ fs, float* __restrict__ qcat)
{
    int idx = blockIdx.x * 256 + threadIdx.x;
    if (idx >= BATCH * H * (DR / 2)) return;
    int i  = idx & 31;
    int bh = idx >> 5;
    int b  = bh >> 7, h = bh & 127;
    const float* src = q + (long long)b * QDIM + h * QKD + DN;
    float x1 = src[2 * i], x2 = src[2 * i + 1];
    float c = fc[i], s = fs[i];
    qcat[(long long)bh * KCAT + KVLR + 2 * i]     = (x1 * c - x2 * s) * SCALE_F;
    qcat[(long long)bh * KCAT + KVLR + 2 * i + 1] = (x1 * s + x2 * c) * SCALE_F;
}

// ---------------- q_abs (FFMA, small) ----------------
__global__ void __launch_bounds__(512) qabs_kernel(
    const float* __restrict__ q, const float* __restrict__ wkvb, float* __restrict__ qcat)
{
    int h = blockIdx.x;
    __shared__ __align__(16) float sq[DN][BATCH];
    int tid = threadIdx.x;
#pragma unroll
    for (int i = 0; i < 8; i++) {
        int idx = tid + i * 512;
        int d = idx >> 5, b = idx & 31;
        sq[d][b] = q[(long long)b * QDIM + h * QKD + d];
    }
    __syncthreads();
    int c = tid;
    ull acc[16];
#pragma unroll
    for (int i = 0; i < 16; i++) acc[i] = 0ull;
    const float* w = wkvb + (long long)h * 256 * KVLR + c;
#pragma unroll 4
    for (int d = 0; d < DN; d++) {
        ull w2 = dup2(w[(long long)d * KVLR]);
#pragma unroll
        for (int bp = 0; bp < 16; bp++) {
            ull qp = *(const ull*)&sq[d][bp * 2];
            acc[bp] = fma2(qp, w2, acc[bp]);
        }
    }
#pragma unroll
    for (int bp = 0; bp < 16; bp++) {
        float2 f = u2f(acc[bp]);
        qcat[((long long)(2 * bp + 0) * H + h) * KCAT + c] = f.x * SCALE_F;
        qcat[((long long)(2 * bp + 1) * H + h) * KCAT + c] = f.y * SCALE_F;
    }
}

// ---------------- KV row loader ----------------
__device__ __forceinline__ void load_kvrow16(float4* rb,
        const float* __restrict__ kvc, const float* __restrict__ pec,
        const float* __restrict__ kvnew, const float* __restrict__ penew,
        int b, int t, int spos, int k0)
{
    const float* src;
    if (k0 < KVLR)
        src = (t == spos) ? (kvnew + (long long)b * KVLR + k0)
                          : (kvc + ((long long)b * MAXS + t) * KVLR + k0);
    else
        src = (t == spos) ? (penew + (long long)b * DR + (k0 - KVLR))
                          : (pec + ((long long)b * MAXS + t) * DR + (k0 - KVLR));
#pragma unroll
    for (int j = 0; j < 4; j++) rb[j] = *(const float4*)(src + j * 4);
}

// =====================================================================
// Fused flash-decode attention.
// Block: 32 heads x 1024 t (one split). 256 threads / 8 warps.
// Per tile of 256 t: S = Q*K^T (MMA) -> online softmax -> O += P*V (MMA).
// Writes partial O (32x512) + (m,l) per row; combine kernel merges splits.
// smem: Aq[576][40] tf32 (92160 B) | Bs/Bv union (66560 B) |
//       Pt[256][40] (40960 B) | corr[32] (128 B)  => 199808 B dynamic
// =====================================================================
#define SM_AQ   0
#define SM_BS   92160
#define SM_PT   (92160 + 66560)
#define SM_CORR (SM_PT + 40960)
#define SM_ATTN (SM_CORR + 128)

__global__ void __launch_bounds__(256, 1) attn_fused(
    const float* __restrict__ qcat, const float* __restrict__ kvc, const float* __restrict__ pec,
    const float* __restrict__ kvnew, const float* __restrict__ penew,
    float* __restrict__ opart, float* __restrict__ ml,
    const int* __restrict__ spos_p)
{
    extern __shared__ char smem_raw[];
    unsigned (*Aq)[40]  = (unsigned(*)[40])(smem_raw + SM_AQ);    // [576][40]
    unsigned (*Bs)[264] = (unsigned(*)[264])(smem_raw + SM_BS);   // [32][264] (2 bufs)
    unsigned (*Bv)[520] = (unsigned(*)[520])(smem_raw + SM_BS);   // [32][520] (2 bufs, union)
    unsigned (*Pt)[40]  = (unsigned(*)[40])(smem_raw + SM_PT);    // [256][40]
    float* corr_s       = (float*)(smem_raw + SM_CORR);           // [32]

    const int h0    = blockIdx.x * 32;
    const int split = blockIdx.y;
    const int b     = blockIdx.z;
    const int spos  = *spos_p;

    const int tid = threadIdx.x, lane = tid & 31, wid = tid >> 5;
    const int gid = lane >> 2, tig = lane & 3;
    const int wt = wid * 32;      // S-phase warp t offset
    const int wc = wid * 64;      // V-phase warp c offset

    // ---- load Q tile (32h x 576k) into Aq (tf32, XOR swizzle) ----
    {
        const float* Qp = qcat + ((long long)b * H + h0) * KCAT;
        const int hh = tid >> 3;
        const int f8 = tid & 7;
#pragma unroll
        for (int j = 0; j < 18; j++) {
            int kq = (f8 + j * 8) * 4;       // 0..572, step 32 per j for fixed f8
            float4 v = *(const float4*)(Qp + (long long)hh * KCAT + kq);
            int col = hh ^ (8 * ((kq >> 2) & 3));
            Aq[kq+0][col] = f2tf(v.x); Aq[kq+1][col] = f2tf(v.y);
            Aq[kq+2][col] = f2tf(v.z); Aq[kq+3][col] = f2tf(v.w);
        }
    }
    __syncthreads();

    // online-softmax state: warp w owns rows 4w..4w+3; 8 lanes per row
    const int hrow = 4 * wid + (lane >> 3);
    const int il = lane & 7;
    float mrow = -1e30f, lrow = 0.f;

    // O accumulator: warp covers 32h x 64c
    float oacc[2][8][4];
#pragma unroll
    for (int mi = 0; mi < 2; mi++)
#pragma unroll
        for (int nj = 0; nj < 8; nj++)
#pragma unroll
            for (int r = 0; r < 4; r++) oacc[mi][nj][r] = 0.f;

    const float* kvb = kvc + (long long)b * MAXS * KVLR;

    for (int it = 0; it < TSPAN / TT; it++) {
        const int t0 = split * TSPAN + it * TT;

        // ================= S phase: S[32h][256t] =================
        float4 rb[4];
        load_kvrow16(rb, kvc, pec, kvnew, penew, b, t0 + tid, spos, 0);
#pragma unroll
        for (int j = 0; j < 4; j++) {
            Bs[j*4+0][tid] = f2tf(rb[j].x); Bs[j*4+1][tid] = f2tf(rb[j].y);
            Bs[j*4+2][tid] = f2tf(rb[j].z); Bs[j*4+3][tid] = f2tf(rb[j].w);
        }
        __syncthreads();

        float sacc[2][4][4];
#pragma unroll
        for (int mi = 0; mi < 2; mi++)
#pragma unroll
            for (int nj = 0; nj < 4; nj++)
#pragma unroll
                for (int r = 0; r < 4; r++) sacc[mi][nj][r] = 0.f;

        for (int cc = 0; cc < KCAT / 16; cc++) {
            const int k0 = cc * 16;
            const bool more = (cc + 1) < KCAT / 16;
            if (more) load_kvrow16(rb, kvc, pec, kvnew, penew, b, t0 + tid, spos, k0 + 16);
            const int bb = (cc & 1) * 16;
#pragma unroll
            for (int s = 0; s < 2; s++) {
                const int kk = s * 8;
                const int kabs = k0 + kk;
                const int key0 = 8 * ((kabs >> 2) & 3);
                const int key1 = 8 * (((kabs >> 2) + 1) & 3);
                unsigned af[2][4];
#pragma unroll
                for (int mi = 0; mi < 2; mi++) {
                    int r0 = mi*16 + gid;
                    af[mi][0] = Aq[kabs+tig  ][ r0    ^ key0];
                    af[mi][1] = Aq[kabs+tig  ][(r0+8) ^ key0];
                    af[mi][2] = Aq[kabs+tig+4][ r0    ^ key1];
                    af[mi][3] = Aq[kabs+tig+4][(r0+8) ^ key1];
                }
                unsigned bf[4][2];
#pragma unroll
                for (int nj = 0; nj < 4; nj++) {
                    bf[nj][0] = Bs[bb+kk+tig  ][wt + nj*8 + gid];
                    bf[nj][1] = Bs[bb+kk+tig+4][wt + nj*8 + gid];
                }
#pragma unroll
                for (int mi = 0; mi < 2; mi++)
#pragma unroll
                    for (int nj = 0; nj < 4; nj++)
                        mma8(sacc[mi][nj], af[mi], bf[nj]);
            }
            __syncthreads();
            if (more) {
                const int nb2 = ((cc + 1) & 1) * 16;
#pragma unroll
                for (int j = 0; j < 4; j++) {
                    Bs[nb2+j*4+0][tid] = f2tf(rb[j].x); Bs[nb2+j*4+1][tid] = f2tf(rb[j].y);
                    Bs[nb2+j*4+2][tid] = f2tf(rb[j].z); Bs[nb2+j*4+3][tid] = f2tf(rb[j].w);
                }
                __syncthreads();
            }
        }

        // write S (f32 bits) to Pt[t][h]
#pragma unroll
        for (int mi = 0; mi < 2; mi++)
#pragma unroll
            for (int nj = 0; nj < 4; nj++) {
                int colb = wt + nj*8 + 2*tig;
                int r = mi*16 + gid;
                Pt[colb  ][r  ] = __float_as_uint(sacc[mi][nj][0]);
                Pt[colb+1][r  ] = __float_as_uint(sacc[mi][nj][1]);
                Pt[colb  ][r+8] = __float_as_uint(sacc[mi][nj][2]);
                Pt[colb+1][r+8] = __float_as_uint(sacc[mi][nj][3]);
            }
        __syncthreads();

        // ================= online softmax on Pt =================
        {
            float mt = -1e30f;
#pragma unroll
            for (int j = 0; j < 32; j++) {
                int tl = il + 8*j;
                float v = __uint_as_float(Pt[tl][hrow]);
                v = (t0 + tl <= spos) ? v : -1e30f;
                mt = fmaxf(mt, v);
            }
#pragma unroll
            for (int o = 1; o < 8; o <<= 1) mt = fmaxf(mt, __shfl_xor_sync(0xffffffffu, mt, o));
            float mnew = fmaxf(mrow, mt);
            float cr = __expf(mrow - mnew);
            float sum = 0.f;
#pragma unroll
            for (int j = 0; j < 32; j++) {
                int tl = il + 8*j;
                float v = __uint_as_float(Pt[tl][hrow]);
                float e = (t0 + tl <= spos) ? __expf(v - mnew) : 0.f;
                sum += e;
                Pt[tl][hrow] = f2tf(e);
            }
#pragma unroll
            for (int o = 1; o < 8; o <<= 1) sum += __shfl_xor_sync(0xffffffffu, sum, o);
            lrow = lrow * cr + sum;
            mrow = mnew;
            if (il == 0) corr_s[hrow] = cr;
        }
        __syncthreads();

        // ================= V phase: O += P(32x256) * KV(256x512) =================
        // rescale O accum
        {
            float crA[2], crB[2];
#pragma unroll
            for (int mi = 0; mi < 2; mi++) {
                crA[mi] = corr_s[mi*16 + gid];
                crB[mi] = corr_s[mi*16 + gid + 8];
            }
#pragma unroll
            for (int mi = 0; mi < 2; mi++)
#pragma unroll
                for (int nj = 0; nj < 8; nj++) {
                    oacc[mi][nj][0] *= crA[mi]; oacc[mi][nj][1] *= crA[mi];
                    oacc[mi][nj][2] *= crB[mi]; oacc[mi][nj][3] *= crB[mi];
                }
        }

        float4 rv[8];
        // prologue: rows t0..t0+15
#pragma unroll
        for (int j = 0; j < 8; j++) {
            int f4id = tid + j * 256;
            int r = f4id >> 7, c4 = (f4id & 127) * 4;
            int t = t0 + r;
            const float* src = (t == spos) ? (kvnew + (long long)b * KVLR + c4)
                                           : (kvb + (long long)t * KVLR + c4);
            rv[j] = *(const float4*)src;
        }
#pragma unroll
        for (int j = 0; j < 8; j++) {
            int f4id = tid + j * 256;
            int r = f4id >> 7, c4 = (f4id & 127) * 4;
            uint4 u = make_uint4(f2tf(rv[j].x), f2tf(rv[j].y), f2tf(rv[j].z), f2tf(rv[j].w));
            *(uint4*)&Bv[r][c4] = u;
        }
        __syncthreads();

        for (int cc = 0; cc < TT / 16; cc++) {
            const int k0 = cc * 16;
            const bool more = (cc + 1) < TT / 16;
            if (more) {
#pragma unroll
                for (int j = 0; j < 8; j++) {
                    int f4id = tid + j * 256;
                    int r = f4id >> 7, c4 = (f4id & 127) * 4;
                    int t = t0 + k0 + 16 + r;
                    const float* src = (t == spos) ? (kvnew + (long long)b * KVLR + c4)
                                                   : (kvb + (long long)t * KVLR + c4);
                    rv[j] = *(const float4*)src;
                }
            }
            const int bb = (cc & 1) * 16;
#pragma unroll
            for (int s = 0; s < 2; s++) {
                const int kk = s * 8;
                unsigned af[2][4];
#pragma unroll
                for (int mi = 0; mi < 2; mi++) {
                    int r0 = mi*16 + gid;
                    af[mi][0] = Pt[k0+kk+tig  ][r0];
                    af[mi][1] = Pt[k0+kk+tig  ][r0+8];
                    af[mi][2] = Pt[k0+kk+tig+4][r0];
                    af[mi][3] = Pt[k0+kk+tig+4][r0+8];
                }
#pragma unroll
                for (int nj = 0; nj < 8; nj++) {
                    unsigned bfa[2];
                    bfa[0] = Bv[bb+kk+tig  ][wc + nj*8 + gid];
                    bfa[1] = Bv[bb+kk+tig+4][wc + nj*8 + gid];
                    mma8(oacc[0][nj], af[0], bfa);
                    mma8(oacc[1][nj], af[1], bfa);
                }
            }
            __syncthreads();
            if (more) {
                const int nb2 = ((cc + 1) & 1) * 16;
#pragma unroll
                for (int j = 0; j < 8; j++) {
                    int f4id = tid + j * 256;
                    int r = f4id >> 7, c4 = (f4id & 127) * 4;
                    uint4 u = make_uint4(f2tf(rv[j].x), f2tf(rv[j].y), f2tf(rv[j].z), f2tf(rv[j].w));
                    *(uint4*)&Bv[nb2 + r][c4] = u;
                }
                __syncthreads();
            }
        }
    }

    // ---- write partials ----
    const long long base = ((long long)(split * BATCH + b) * H + h0);
#pragma unroll
    for (int mi = 0; mi < 2; mi++)
#pragma unroll
        for (int nj = 0; nj < 8; nj++) {
            int r = mi*16 + gid;
            int colc = wc + nj*8 + 2*tig;
            float* op = opart + (base + r) * KVLR + colc;
            op[0] = oacc[mi][nj][0];
            op[1] = oacc[mi][nj][1];
            float* op2 = opart + (base + r + 8) * KVLR + colc;
            op2[0] = oacc[mi][nj][2];
            op2[1] = oacc[mi][nj][3];
        }
    if (il == 0)
        ((float2*)ml)[base + hrow] = make_float2(mrow, lrow);
}

// ---------------- combine splits ----------------
__global__ void __launch_bounds__(128) attn_combine(
    const float* __restrict__ opart, const float* __restrict__ ml, float* __restrict__ olat)
{
    const int row = blockIdx.x;                 // b*H + h
    const long long stride = (long long)BATCH * H;
    float m[NSPLIT], l[NSPLIT];
#pragma unroll
    for (int i = 0; i < NSPLIT; i++) {
        float2 v = ((const float2*)ml)[stride * i + row];
        m[i] = v.x; l[i] = v.y;
    }
    float M = m[0];
#pragma unroll
    for (int i = 1; i < NSPLIT; i++) M = fmaxf(M, m[i]);
    float L = 0.f, w[NSPLIT];
#pragma unroll
    for (int i = 0; i < NSPLIT; i++) { w[i] = __expf(m[i] - M); L += w[i] * l[i]; }
    const float inv = 1.f / L;
    const int c = threadIdx.x * 4;
    float4 o = make_float4(0,0,0,0);
#pragma unroll
    for (int i = 0; i < NSPLIT; i++) {
        float4 p = *(const float4*)&opart[(stride * i + row) * KVLR + c];
        o.x += w[i]*p.x; o.y += w[i]*p.y; o.z += w[i]*p.z; o.w += w[i]*p.w;
    }
    o.x *= inv; o.y *= inv; o.z *= inv; o.w *= inv;
    *(float4*)&olat[(long long)row * KVLR + c] = o;
}

// =====================================================================
// FFMA split-K GEMV (kvfull, ohead)
// =====================================================================
template<int BN, int TN>
__global__ void __launch_bounds__(256) gemv_splitk(
    const float* __restrict__ A, const float* __restrict__ B, float* __restrict__ C,
    int N, int lda, int ldb, int ldc, int kChunk,
    long long aB, long long bB, long long cB)
{
    A += (long long)blockIdx.z * aB;
    B += (long long)blockIdx.z * bB;
    C += (long long)blockIdx.z * cB;
    const int n0 = blockIdx.x * BN;
    const int ks = blockIdx.y * kChunk;
    const int ke = ks + kChunk;

    __shared__ __align__(16) ull   As2[16][32];
    __shared__ __align__(16) float Bsf [16][BN];

    const int tid = threadIdx.x;
    const int tx = tid & 31, ty = tid >> 5;

    const bool aon = tid < 128;
    const int am = tid >> 2, akq = (tid & 3) << 2;
    constexpr int PER = BN / 64;
    const int bn  = tid % BN;
    const int bkq = (tid / BN) * PER;
    const bool bon = (n0 + bn) < N;

    float4 ra = make_float4(0,0,0,0);
    float4 rb[PER];
#pragma unroll
    for (int j = 0; j < PER; j++) rb[j] = make_float4(0,0,0,0);

    if (aon) ra = *(const float4*)(A + (long long)am * lda + ks + akq);
    if (bon) {
        const float* bp = B + (long long)(n0 + bn) * ldb + ks + bkq * 4;
#pragma unroll
        for (int j = 0; j < PER; j++) rb[j] = *(const float4*)(bp + j * 4);
    }
    if (aon) {
        As2[akq+0][am] = dup2(ra.x); As2[akq+1][am] = dup2(ra.y);
        As2[akq+2][am] = dup2(ra.z); As2[akq+3][am] = dup2(ra.w);
    }
#pragma unroll
    for (int j = 0; j < PER; j++) {
        Bsf[(bkq+j)*4+0][bn] = rb[j].x;
        Bsf[(bkq+j)*4+1][bn] = rb[j].y;
        Bsf[(bkq+j)*4+2][bn] = rb[j].z;
        Bsf[(bkq+j)*4+3][bn] = rb[j].w;
    }
    __syncthreads();

    ull acc[4][TN/2];
#pragma unroll
    for (int m = 0; m < 4; m++)
#pragma unroll
        for (int j = 0; j < TN/2; j++) acc[m][j] = 0ull;

    for (int k0 = ks; k0 < ke; k0 += 16) {
        const bool more = (k0 + 16) < ke;
        if (more) {
            if (aon) ra = *(const float4*)(A + (long long)am * lda + (k0+16) + akq);
            if (bon) {
                const float* bp = B + (long long)(n0 + bn) * ldb + (k0+16) + bkq * 4;
#pragma unroll
                for (int j = 0; j < PER; j++) rb[j] = *(const float4*)(bp + j * 4);
            }
        }
#pragma unroll
        for (int kk = 0; kk < 16; kk++) {
            ulonglong2 a01 = *(const ulonglong2*)&As2[kk][ty*4];
            ulonglong2 a23 = *(const ulonglong2*)&As2[kk][ty*4+2];
            ull a[4] = {a01.x, a01.y, a23.x, a23.y};
            ull bq[TN/2];
            if constexpr (TN == 8) {
                ulonglong2 b0 = *(const ulonglong2*)&Bsf[kk][tx*8];
                ulonglong2 b1 = *(const ulonglong2*)&Bsf[kk][tx*8+4];
                bq[0]=b0.x; bq[1]=b0.y; bq[2]=b1.x; bq[3]=b1.y;
            } else {
                ulonglong2 b0 = *(const ulonglong2*)&Bsf[kk][tx*4];
                bq[0]=b0.x; bq[1]=b0.y;
            }
#pragma unroll
            for (int m = 0; m < 4; m++)
#pragma unroll
                for (int j = 0; j < TN/2; j++)
                    acc[m][j] = fma2(a[m], bq[j], acc[m][j]);
        }
        __syncthreads();
        if (more) {
            if (aon) {
                As2[akq+0][am] = dup2(ra.x); As2[akq+1][am] = dup2(ra.y);
                As2[akq+2][am] = dup2(ra.z); As2[akq+3][am] = dup2(ra.w);
            }
#pragma unroll
            for (int j = 0; j < PER; j++) {
                Bsf[(bkq+j)*4+0][bn] = rb[j].x;
                Bsf[(bkq+j)*4+1][bn] = rb[j].y;
                Bsf[(bkq+j)*4+2][bn] = rb[j].z;
                Bsf[(bkq+j)*4+3][bn] = rb[j].w;
            }
        }
        __syncthreads();
    }

    const int nb = n0 + tx * TN;
#pragma unroll
    for (int m = 0; m < 4; m++) {
        float* cp = C + (long long)(ty*4+m) * ldc + nb;
#pragma unroll
        for (int j = 0; j < TN/2; j++) {
            float2 f = u2f(acc[m][j]);
            if (nb + 2*j     < N) atomicAdd(cp + 2*j,     f.x);
            if (nb + 2*j + 1 < N) atomicAdd(cp + 2*j + 1, f.y);
        }
    }
}

// ---------------- launch ----------------
extern "C" void kernel_launch(void* const* d_in, const int* in_sizes, int n_in,
                              void* d_out, int out_size)
{
    const float* x        = (const float*)d_in[0];
    const float* fc       = (const float*)d_in[1];
    const float* fs       = (const float*)d_in[2];
    const float* kvc      = (const float*)d_in[3];
    const float* pec      = (const float*)d_in[4];
    const float* wq_a     = (const float*)d_in[5];
    const float* q_norm_w = (const float*)d_in[6];
    const float* wq_b     = (const float*)d_in[7];
    const float* wkv_a    = (const float*)d_in[8];
    const float* kv_norm  = (const float*)d_in[9];
    const float* wkv_b    = (const float*)d_in[10];
    const float* wo       = (const float*)d_in[11];
    const int*   spos     = (const int*)d_in[12];
    float*       out      = (float*)d_out;

    float *qlat, *kvfull, *kvnew, *penew, *q, *qcat, *opart, *ml, *olat, *ohead;
    cudaGetSymbolAddress((void**)&qlat,   g_qlat);
    cudaGetSymbolAddress((void**)&kvfull, g_kvfull);
    cudaGetSymbolAddress((void**)&kvnew,  g_kvnew);
    cudaGetSymbolAddress((void**)&penew,  g_penew);
    cudaGetSymbolAddress((void**)&q,      g_q);
    cudaGetSymbolAddress((void**)&qcat,   g_qcat);
    cudaGetSymbolAddress((void**)&opart,  g_opart);
    cudaGetSymbolAddress((void**)&ml,     g_ml);
    cudaGetSymbolAddress((void**)&olat,   g_olat);
    cudaGetSymbolAddress((void**)&ohead,  g_ohead);

    static int smem_set = 0;
    if (!smem_set) {
        cudaFuncSetAttribute(attn_fused, cudaFuncAttributeMaxDynamicSharedMemorySize, SM_ATTN);
        smem_set = 1;
    }

    cudaMemsetAsync(qlat,   0, (size_t)BATCH * QLR  * 4);
    cudaMemsetAsync(kvfull, 0, (size_t)BATCH * KCAT * 4);
    cudaMemsetAsync(q,      0, (size_t)BATCH * QDIM * 4);
    cudaMemsetAsync(ohead,  0, (size_t)BATCH * ODIM * 4);
    cudaMemsetAsync(out,    0, (size_t)out_size * 4);

    dim3 blk(256);

    // q_lat = x @ wq_a^T   (N=1536, K=7168)
    gemv_mma<<<dim3(6,16,1), blk>>>(x, wq_a, qlat, DIM, DIM, QLR, 448);
    // kv_full = x @ wkv_a^T (N=576, K=7168)
    gemv_splitk<256,8><<<dim3(3,32,1), blk>>>(x, wkv_a, kvfull, KCAT, DIM, DIM, KCAT, 224, 0,0,0);
    rmsnorm_kernel<<<32, 256>>>(qlat, q_norm_w, QLR);
    kvprep_kernel<<<32, 256>>>(kvfull, kv_norm, fc, fs, kvnew, penew);
    // q = q_lat @ wq_b^T   (N=24576, K=1536)
    gemv_mma<<<dim3(96,3,1), blk>>>(qlat, wq_b, q, QLR, QLR, QDIM, 512);
    qrope_kernel<<<512, 256>>>(q, fc, fs, qcat);
    qabs_kernel<<<128, 512>>>(q, wkv_b, qcat);
    // fused flash attention
    attn_fused<<<dim3(H/32, NSPLIT, BATCH), blk, SM_ATTN>>>(
        qcat, kvc, pec, kvnew, penew, opart, ml, spos);
    attn_combine<<<BATCH * H, 128>>>(opart, ml, olat);
    // ohead per head
    gemv_splitk<128,4><<<dim3(1,1,H), blk>>>(olat, wkv_b + 128*KVLR, ohead,
                                             DV, H*KVLR, KVLR, ODIM, KVLR,
                                             (long long)KVLR, (long long)256*KVLR, (long long)DV);
    // out = ohead @ wo^T   (N=7168, K=16384)
    gemv_mma<<<dim3(28,8,1), blk>>>(ohead, wo, out, ODIM, ODIM, DIM, 2048);
}

// round 6
// speedup vs baseline: 1.4995x; 1.4995x over previous
#include <cuda_runtime.h>
#include <cuda_bf16.h>

// ---------------- problem constants ----------------
#define BATCH 32
#define DIM   7168
#define H     128
#define QLR   1536
#define KVLR  512
#define DN    128
#define DR    64
#define DV    128
#define QKD   192
#define MAXS  4096
#define QDIM  (H*QKD)      // 24576
#define KCAT  (KVLR+DR)    // 576
#define ODIM  (H*DV)       // 16384
#define NBLK  (MAXS/256)   // 16 t-blocks

#define SCALE_F 0.07216878364870322f
#define EPS_F   1e-6f

typedef unsigned long long ull;

// ---------------- helpers ----------------
__device__ __forceinline__ ull fma2(ull a, ull b, ull c) {
    ull d;
    asm("fma.rn.f32x2 %0, %1, %2, %3;" : "=l"(d) : "l"(a), "l"(b), "l"(c));
    return d;
}
__device__ __forceinline__ ull dup2(float x) {
    ull d;
    asm("mov.b64 %0, {%1, %1};" : "=l"(d) : "f"(x));
    return d;
}
__device__ __forceinline__ float2 u2f(ull v) {
    float2 f;
    f.x = __uint_as_float((unsigned)(v & 0xffffffffull));
    f.y = __uint_as_float((unsigned)(v >> 32));
    return f;
}
__device__ __forceinline__ unsigned f2tf(float f) {
    unsigned u; asm("cvt.rna.tf32.f32 %0, %1;" : "=r"(u) : "f"(f)); return u;
}
__device__ __forceinline__ void mma8(float* c, const unsigned* a, const unsigned* b) {
    asm volatile("mma.sync.aligned.m16n8k8.row.col.f32.tf32.tf32.f32 "
                 "{%0,%1,%2,%3}, {%4,%5,%6,%7}, {%8,%9}, {%0,%1,%2,%3};"
                 : "+f"(c[0]), "+f"(c[1]), "+f"(c[2]), "+f"(c[3])
                 : "r"(a[0]), "r"(a[1]), "r"(a[2]), "r"(a[3]),
                   "r"(b[0]), "r"(b[1]));
}

// ---------------- scratch ----------------
__device__ __align__(16) float g_qlat  [BATCH * QLR];
__device__ __align__(16) float g_kvfull[BATCH * KCAT];
__device__ __align__(16) float g_kvnew [BATCH * KVLR];
__device__ __align__(16) float g_penew [BATCH * DR];
__device__ __align__(16) float g_q     [BATCH * QDIM];
__device__ __align__(16) float g_qcat  [BATCH * H * KCAT];
__device__ __align__(16) float g_scores[(long long)BATCH * H * MAXS];
__device__ __align__(16) float g_ml    [BATCH * H * NBLK * 2];
__device__ __align__(16) float g_w     [BATCH * H * NBLK];
__device__ __align__(16) float g_olat  [BATCH * H * KVLR];
__device__ __align__(16) float g_ohead [BATCH * ODIM];

// ---------------- reductions ----------------
__device__ __forceinline__ float warpSum(float v) {
#pragma unroll
    for (int o = 16; o; o >>= 1) v += __shfl_xor_sync(0xffffffffu, v, o);
    return v;
}
__device__ __forceinline__ float blockSum256(float v) {
    __shared__ float sm[8];
    int lane = threadIdx.x & 31, w = threadIdx.x >> 5;
    __syncthreads();
    v = warpSum(v);
    if (!lane) sm[w] = v;
    __syncthreads();
    float r = 0.f;
#pragma unroll
    for (int i = 0; i < 8; i++) r += sm[i];
    return r;
}

// =====================================================================
// TF32 MMA split-K GEMV (proven round-4 kernel)
// =====================================================================
__global__ void __launch_bounds__(256) gemv_mma(
    const float* __restrict__ A, const float* __restrict__ B, float* __restrict__ C,
    int lda, int ldb, int ldc, int kChunk)
{
    const int n0 = blockIdx.x * 256;
    const int ks = blockIdx.y * kChunk;
    const int ke = ks + kChunk;

    __shared__ unsigned As[16][40];
    __shared__ unsigned Bs[16][264];

    const int tid = threadIdx.x, lane = tid & 31, wid = tid >> 5;
    const int gid = lane >> 2, tig = lane & 3;
    const int wn = wid * 32;

    const bool aon = tid < 128;
    const int am = tid >> 2, akq = (tid & 3) * 4;
    const int aq = (akq >> 2) & 3;
    const long long brow = (long long)(n0 + tid) * ldb;

    float4 ra = make_float4(0,0,0,0);
    float4 rb[4];

    if (aon) ra = *(const float4*)(A + (long long)am * lda + ks + akq);
#pragma unroll
    for (int j = 0; j < 4; j++) rb[j] = *(const float4*)(B + brow + ks + j*4);

    if (aon) {
        int col = am ^ (8*aq);
        As[akq+0][col] = f2tf(ra.x); As[akq+1][col] = f2tf(ra.y);
        As[akq+2][col] = f2tf(ra.z); As[akq+3][col] = f2tf(ra.w);
    }
#pragma unroll
    for (int j = 0; j < 4; j++) {
        Bs[j*4+0][tid] = f2tf(rb[j].x); Bs[j*4+1][tid] = f2tf(rb[j].y);
        Bs[j*4+2][tid] = f2tf(rb[j].z); Bs[j*4+3][tid] = f2tf(rb[j].w);
    }
    __syncthreads();

    float acc[2][4][4];
#pragma unroll
    for (int mi = 0; mi < 2; mi++)
#pragma unroll
        for (int nj = 0; nj < 4; nj++)
#pragma unroll
            for (int r = 0; r < 4; r++) acc[mi][nj][r] = 0.f;

    for (int k0 = ks; k0 < ke; k0 += 16) {
        const bool more = (k0 + 16) < ke;
        if (more) {
            if (aon) ra = *(const float4*)(A + (long long)am * lda + (k0+16) + akq);
#pragma unroll
            for (int j = 0; j < 4; j++) rb[j] = *(const float4*)(B + brow + (k0+16) + j*4);
        }
#pragma unroll
        for (int s = 0; s < 2; s++) {
            const int kk = s * 8;
            const int key0 = 8 * ((kk >> 2) & 3);
            const int key1 = 8 * (((kk >> 2) + 1) & 3);
            unsigned af[2][4];
#pragma unroll
            for (int mi = 0; mi < 2; mi++) {
                int r0 = mi*16 + gid;
                af[mi][0] = As[kk+tig  ][ r0    ^ key0];
                af[mi][1] = As[kk+tig  ][(r0+8) ^ key0];
                af[mi][2] = As[kk+tig+4][ r0    ^ key1];
                af[mi][3] = As[kk+tig+4][(r0+8) ^ key1];
            }
            unsigned bf[4][2];
#pragma unroll
            for (int nj = 0; nj < 4; nj++) {
                bf[nj][0] = Bs[kk+tig  ][wn + nj*8 + gid];
                bf[nj][1] = Bs[kk+tig+4][wn + nj*8 + gid];
            }
#pragma unroll
            for (int mi = 0; mi < 2; mi++)
#pragma unroll
                for (int nj = 0; nj < 4; nj++)
                    mma8(acc[mi][nj], af[mi], bf[nj]);
        }
        __syncthreads();
        if (more) {
            if (aon) {
                int col = am ^ (8*aq);
                As[akq+0][col] = f2tf(ra.x); As[akq+1][col] = f2tf(ra.y);
                As[akq+2][col] = f2tf(ra.z); As[akq+3][col] = f2tf(ra.w);
            }
#pragma unroll
            for (int j = 0; j < 4; j++) {
                Bs[j*4+0][tid] = f2tf(rb[j].x); Bs[j*4+1][tid] = f2tf(rb[j].y);
                Bs[j*4+2][tid] = f2tf(rb[j].z); Bs[j*4+3][tid] = f2tf(rb[j].w);
            }
        }
        __syncthreads();
    }

#pragma unroll
    for (int mi = 0; mi < 2; mi++)
#pragma unroll
        for (int nj = 0; nj < 4; nj++) {
            float* cp = C + (long long)(mi*16+gid)*ldc + n0 + wn + nj*8 + 2*tig;
            atomicAdd(cp,           acc[mi][nj][0]);
            atomicAdd(cp + 1,       acc[mi][nj][1]);
            atomicAdd(cp + 8*ldc,   acc[mi][nj][2]);
            atomicAdd(cp + 8*ldc+1, acc[mi][nj][3]);
        }
}

// ---------------- rmsnorm (in place) ----------------
__global__ void __launch_bounds__(256) rmsnorm_kernel(float* __restrict__ v,
                                                      const float* __restrict__ w, int n)
{
    int b = blockIdx.x;
    float* row = v + (long long)b * n;
    float ss = 0.f;
    for (int i = threadIdx.x; i < n; i += 256) { float x = row[i]; ss += x * x; }
    ss = blockSum256(ss);
    __shared__ float s_scale;
    if (threadIdx.x == 0) s_scale = rsqrtf(ss / (float)n + EPS_F);
    __syncthreads();
    float sc = s_scale;
    for (int i = threadIdx.x; i < n; i += 256) row[i] = row[i] * sc * w[i];
}

// ---------------- kv prep ----------------
__global__ void __launch_bounds__(256) kvprep_kernel(
    const float* __restrict__ kvfull, const float* __restrict__ w,
    const float* __restrict__ fc, const float* __restrict__ fs,
    float* __restrict__ kvnew, float* __restrict__ penew)
{
    int b = blockIdx.x;
    const float* row = kvfull + (long long)b * KCAT;
    float ss = 0.f;
    for (int i = threadIdx.x; i < KVLR; i += 256) { float x = row[i]; ss += x * x; }
    ss = blockSum256(ss);
    __shared__ float s_scale;
    if (threadIdx.x == 0) s_scale = rsqrtf(ss / (float)KVLR + EPS_F);
    __syncthreads();
    float sc = s_scale;
    for (int i = threadIdx.x; i < KVLR; i += 256)
        kvnew[(long long)b * KVLR + i] = row[i] * sc * w[i];
    if (threadIdx.x < 32) {
        int i = threadIdx.x;
        float x1 = row[KVLR + 2 * i], x2 = row[KVLR + 2 * i + 1];
        float c = fc[i], s = fs[i];
        penew[(long long)b * DR + 2 * i]     = x1 * c - x2 * s;
        penew[(long long)b * DR + 2 * i + 1] = x1 * s + x2 * c;
    }
}

// ---------------- q rope -> qcat tail (scaled) ----------------
__global__ void __launch_bounds__(256) qrope_kernel(
    const float* __restrict__ q, const float* __restrict__ fc,
    const float* __restrict__ fs, float* __restrict__ qcat)
{
    int idx = blockIdx.x * 256 + threadIdx.x;
    if (idx >= BATCH * H * (DR / 2)) return;
    int i  = idx & 31;
    int bh = idx >> 5;
    int b  = bh >> 7, h = bh & 127;
    const float* src = q + (long long)b * QDIM + h * QKD + DN;
    float x1 = src[2 * i], x2 = src[2 * i + 1];
    float c = fc[i], s = fs[i];
    qcat[(long long)bh * KCAT + KVLR + 2 * i]     = (x1 * c - x2 * s) * SCALE_F;
    qcat[(long long)bh * KCAT + KVLR + 2 * i + 1] = (x1 * s + x2 * c) * SCALE_F;
}

// ---------------- q_abs (FFMA, small) ----------------
__global__ void __launch_bounds__(512) qabs_kernel(
    const float* __restrict__ q, const float* __restrict__ wkvb, float* __restrict__ qcat)
{
    int h = blockIdx.x;
    __shared__ __align__(16) float sq[DN][BATCH];
    int tid = threadIdx.x;
#pragma unroll
    for (int i = 0; i < 8; i++) {
        int idx = tid + i * 512;
        int d = idx >> 5, b = idx & 31;
        sq[d][b] = q[(long long)b * QDIM + h * QKD + d];
    }
    __syncthreads();
    int c = tid;
    ull acc[16];
#pragma unroll
    for (int i = 0; i < 16; i++) acc[i] = 0ull;
    const float* w = wkvb + (long long)h * 256 * KVLR + c;
#pragma unroll 4
    for (int d = 0; d < DN; d++) {
        ull w2 = dup2(w[(long long)d * KVLR]);
#pragma unroll
        for (int bp = 0; bp < 16; bp++) {
            ull qp = *(const ull*)&sq[d][bp * 2];
            acc[bp] = fma2(qp, w2, acc[bp]);
        }
    }
#pragma unroll
    for (int bp = 0; bp < 16; bp++) {
        float2 f = u2f(acc[bp]);
        qcat[((long long)(2 * bp + 0) * H + h) * KCAT + c] = f.x * SCALE_F;
        qcat[((long long)(2 * bp + 1) * H + h) * KCAT + c] = f.y * SCALE_F;
    }
}

// ---------------- KV row loader ----------------
__device__ __forceinline__ void load_kvrow16(float4* rb,
        const float* __restrict__ kvc, const float* __restrict__ pec,
        const float* __restrict__ kvnew, const float* __restrict__ penew,
        int b, int t, int spos, int k0)
{
    const float* src;
    if (k0 < KVLR)
        src = (t == spos) ? (kvnew + (long long)b * KVLR + k0)
                          : (kvc + ((long long)b * MAXS + t) * KVLR + k0);
    else
        src = (t == spos) ? (penew + (long long)b * DR + (k0 - KVLR))
                          : (pec + ((long long)b * MAXS + t) * DR + (k0 - KVLR));
#pragma unroll
    for (int j = 0; j < 4; j++) rb[j] = *(const float4*)(src + j * 4);
}

// =====================================================================
// scores + block-local softmax: writes P' = exp(s - m_blk) and (m,l)
// tile 64h x 256t, warps 2x4 (32h x 64t each)
// =====================================================================
__global__ void __launch_bounds__(256) scores_sm(
    const float* __restrict__ qcat, const float* __restrict__ kvc, const float* __restrict__ pec,
    const float* __restrict__ kvnew, const float* __restrict__ penew,
    float* __restrict__ S, float2* __restrict__ mlv, const int* __restrict__ spos_p)
{
    const int b = blockIdx.z, spos = *spos_p;
    const int t0 = blockIdx.x * 256, h0 = blockIdx.y * 64;
    const float* A = qcat + ((long long)b * H + h0) * KCAT;
    float* C = S + ((long long)b * H + h0) * MAXS;

    __shared__ unsigned As[16][72];
    __shared__ unsigned Bs[16][264];
    __shared__ float red[64][4];

    const int tid = threadIdx.x, lane = tid & 31, wid = tid >> 5;
    const int gid = lane >> 2, tig = lane & 3;
    const int wh = (wid & 1) * 32, wt = (wid >> 1) * 64;
    const int wtq = wid >> 1;

    const int ah = tid >> 2, akq = (tid & 3) * 4;
    const int acol = ah ^ (8 * ((akq >> 2) & 3));
    const int bt = t0 + tid;

    float4 ra; float4 rb[4];
    ra = *(const float4*)(A + (long long)ah * KCAT + akq);
    load_kvrow16(rb, kvc, pec, kvnew, penew, b, bt, spos, 0);
    As[akq+0][acol] = f2tf(ra.x); As[akq+1][acol] = f2tf(ra.y);
    As[akq+2][acol] = f2tf(ra.z); As[akq+3][acol] = f2tf(ra.w);
#pragma unroll
    for (int j = 0; j < 4; j++) {
        Bs[j*4+0][tid] = f2tf(rb[j].x); Bs[j*4+1][tid] = f2tf(rb[j].y);
        Bs[j*4+2][tid] = f2tf(rb[j].z); Bs[j*4+3][tid] = f2tf(rb[j].w);
    }
    __syncthreads();

    float acc[2][8][4];
#pragma unroll
    for (int mi = 0; mi < 2; mi++)
#pragma unroll
        for (int nj = 0; nj < 8; nj++)
#pragma unroll
            for (int r = 0; r < 4; r++) acc[mi][nj][r] = 0.f;

    for (int k0 = 0; k0 < KCAT; k0 += 16) {
        const bool more = (k0 + 16) < KCAT;
        if (more) {
            ra = *(const float4*)(A + (long long)ah * KCAT + (k0+16) + akq);
            load_kvrow16(rb, kvc, pec, kvnew, penew, b, bt, spos, k0 + 16);
        }
#pragma unroll
        for (int s = 0; s < 2; s++) {
            const int kk = s * 8;
            const int key0 = 8 * ((kk >> 2) & 3);
            const int key1 = 8 * (((kk >> 2) + 1) & 3);
            unsigned af[2][4];
#pragma unroll
            for (int mi = 0; mi < 2; mi++) {
                int r0 = wh + mi*16 + gid;
                af[mi][0] = As[kk+tig  ][ r0    ^ key0];
                af[mi][1] = As[kk+tig  ][(r0+8) ^ key0];
                af[mi][2] = As[kk+tig+4][ r0    ^ key1];
                af[mi][3] = As[kk+tig+4][(r0+8) ^ key1];
            }
            unsigned bf[8][2];
#pragma unroll
            for (int nj = 0; nj < 8; nj++) {
                bf[nj][0] = Bs[kk+tig  ][wt + nj*8 + gid];
                bf[nj][1] = Bs[kk+tig+4][wt + nj*8 + gid];
            }
#pragma unroll
            for (int mi = 0; mi < 2; mi++)
#pragma unroll
                for (int nj = 0; nj < 8; nj++)
                    mma8(acc[mi][nj], af[mi], bf[nj]);
        }
        __syncthreads();
        if (more) {
            As[akq+0][acol] = f2tf(ra.x); As[akq+1][acol] = f2tf(ra.y);
            As[akq+2][acol] = f2tf(ra.z); As[akq+3][acol] = f2tf(ra.w);
#pragma unroll
            for (int j = 0; j < 4; j++) {
                Bs[j*4+0][tid] = f2tf(rb[j].x); Bs[j*4+1][tid] = f2tf(rb[j].y);
                Bs[j*4+2][tid] = f2tf(rb[j].z); Bs[j*4+3][tid] = f2tf(rb[j].w);
            }
            __syncthreads();
        }
    }

    // ---------------- block-local softmax epilogue ----------------
    float m_lo[2], m_hi[2];
#pragma unroll
    for (int mi = 0; mi < 2; mi++) {
        float a = -1e30f, c = -1e30f;
#pragma unroll
        for (int nj = 0; nj < 8; nj++) {
            int t = t0 + wt + nj*8 + 2*tig;
            float v0 = (t     <= spos) ? acc[mi][nj][0] : -1e30f;
            float v1 = (t + 1 <= spos) ? acc[mi][nj][1] : -1e30f;
            float v2 = (t     <= spos) ? acc[mi][nj][2] : -1e30f;
            float v3 = (t + 1 <= spos) ? acc[mi][nj][3] : -1e30f;
            a = fmaxf(a, fmaxf(v0, v1));
            c = fmaxf(c, fmaxf(v2, v3));
        }
        a = fmaxf(a, __shfl_xor_sync(0xffffffffu, a, 1));
        a = fmaxf(a, __shfl_xor_sync(0xffffffffu, a, 2));
        c = fmaxf(c, __shfl_xor_sync(0xffffffffu, c, 1));
        c = fmaxf(c, __shfl_xor_sync(0xffffffffu, c, 2));
        m_lo[mi] = a; m_hi[mi] = c;
    }
    if (tig == 0) {
#pragma unroll
        for (int mi = 0; mi < 2; mi++) {
            red[wh + mi*16 + gid    ][wtq] = m_lo[mi];
            red[wh + mi*16 + gid + 8][wtq] = m_hi[mi];
        }
    }
    __syncthreads();
#pragma unroll
    for (int mi = 0; mi < 2; mi++) {
        int r = wh + mi*16 + gid;
        m_lo[mi] = fmaxf(fmaxf(red[r][0],   red[r][1]),   fmaxf(red[r][2],   red[r][3]));
        m_hi[mi] = fmaxf(fmaxf(red[r+8][0], red[r+8][1]), fmaxf(red[r+8][2], red[r+8][3]));
    }
    __syncthreads();
    float s_lo[2] = {0.f, 0.f}, s_hi[2] = {0.f, 0.f};
#pragma unroll
    for (int mi = 0; mi < 2; mi++) {
#pragma unroll
        for (int nj = 0; nj < 8; nj++) {
            int t = t0 + wt + nj*8 + 2*tig;
            float e0 = (t     <= spos) ? __expf(acc[mi][nj][0] - m_lo[mi]) : 0.f;
            float e1 = (t + 1 <= spos) ? __expf(acc[mi][nj][1] - m_lo[mi]) : 0.f;
            float e2 = (t     <= spos) ? __expf(acc[mi][nj][2] - m_hi[mi]) : 0.f;
            float e3 = (t + 1 <= spos) ? __expf(acc[mi][nj][3] - m_hi[mi]) : 0.f;
            acc[mi][nj][0] = e0; acc[mi][nj][1] = e1;
            acc[mi][nj][2] = e2; acc[mi][nj][3] = e3;
            s_lo[mi] += e0 + e1; s_hi[mi] += e2 + e3;
        }
        s_lo[mi] += __shfl_xor_sync(0xffffffffu, s_lo[mi], 1);
        s_lo[mi] += __shfl_xor_sync(0xffffffffu, s_lo[mi], 2);
        s_hi[mi] += __shfl_xor_sync(0xffffffffu, s_hi[mi], 1);
        s_hi[mi] += __shfl_xor_sync(0xffffffffu, s_hi[mi], 2);
    }
    if (tig == 0) {
#pragma unroll
        for (int mi = 0; mi < 2; mi++) {
            red[wh + mi*16 + gid    ][wtq] = s_lo[mi];
            red[wh + mi*16 + gid + 8][wtq] = s_hi[mi];
        }
    }
    __syncthreads();
    if (wtq == 0 && tig == 0) {
#pragma unroll
        for (int mi = 0; mi < 2; mi++) {
            int r = wh + mi*16 + gid;
            float l0 = red[r][0]   + red[r][1]   + red[r][2]   + red[r][3];
            float l1 = red[r+8][0] + red[r+8][1] + red[r+8][2] + red[r+8][3];
            mlv[((long long)(b * H + h0 + r))     * NBLK + blockIdx.x] = make_float2(m_lo[mi], l0);
            mlv[((long long)(b * H + h0 + r + 8)) * NBLK + blockIdx.x] = make_float2(m_hi[mi], l1);
        }
    }

    // write P'
#pragma unroll
    for (int mi = 0; mi < 2; mi++)
#pragma unroll
        for (int nj = 0; nj < 8; nj++) {
            float* cp = C + (long long)(wh + mi*16 + gid) * MAXS + t0 + wt + nj*8 + 2*tig;
            *(float2*)cp            = make_float2(acc[mi][nj][0], acc[mi][nj][1]);
            *(float2*)(cp + 8*MAXS) = make_float2(acc[mi][nj][2], acc[mi][nj][3]);
        }
}

// ---------------- combine weights: w[row][blk] = exp(m_blk - M)/L ----------------
__global__ void __launch_bounds__(256) wcomb_kernel(
    const float2* __restrict__ mlv, float* __restrict__ wv)
{
    int row = blockIdx.x * 256 + threadIdx.x;
    if (row >= BATCH * H) return;
    const float2* p = mlv + (long long)row * NBLK;
    float2 v[NBLK];
    float M = -1e30f;
#pragma unroll
    for (int i = 0; i < NBLK; i++) { v[i] = p[i]; M = fmaxf(M, v[i].x); }
    float L = 0.f;
#pragma unroll
    for (int i = 0; i < NBLK; i++) L += __expf(v[i].x - M) * v[i].y;
    float inv = 1.f / L;
#pragma unroll
    for (int i = 0; i < NBLK; i++)
        wv[(long long)row * NBLK + i] = __expf(v[i].x - M) * inv;
}

// =====================================================================
// olat: O[b,h,c] = sum_blk w[h][blk] sum_t P'[h,t] kv[t,c]
// tile 64h x 256c, warps 2x4 (32h x 64c), split-k over t (2), atomicAdd
// =====================================================================
__global__ void __launch_bounds__(256) olat_w(
    const float* __restrict__ P, const float* __restrict__ kvc,
    const float* __restrict__ kvnew, const float* __restrict__ wv,
    float* __restrict__ O, const int* __restrict__ spos_p)
{
    const int b = blockIdx.z, spos = *spos_p;
    const int c0 = blockIdx.x * 256;
    const int hb = blockIdx.y >> 1, ks = blockIdx.y & 1;
    const int h0 = hb * 64;
    const float* A = P + ((long long)b * H + h0) * MAXS;
    float* C = O + ((long long)b * H + h0) * KVLR;

    __shared__ unsigned As[16][72];
    __shared__ unsigned Bs[16][264];
    __shared__ float ws[64][16];

    const int tid = threadIdx.x, lane = tid & 31, wid = tid >> 5;
    const int gid = lane >> 2, tig = lane & 3;
    const int wh = (wid & 1) * 32, wc = (wid >> 1) * 64;

    // cache per-row block weights
#pragma unroll
    for (int j = 0; j < 4; j++) {
        int idx = tid * 4 + j;
        int r = idx >> 4, blk = idx & 15;
        ws[r][blk] = wv[((long long)(b * H + h0 + r)) * NBLK + blk];
    }
    __syncthreads();

    const int ah = tid >> 2, akq = (tid & 3) * 4;
    const int acol = ah ^ (8 * ((akq >> 2) & 3));
    const int kbeg = ks * (MAXS/2), kend = kbeg + (MAXS/2);

    float4 ra; float4 rb[4];
    {
        float w0 = ws[ah][kbeg >> 8];
        ra = *(const float4*)(A + (long long)ah * MAXS + kbeg + akq);
        ra.x *= w0; ra.y *= w0; ra.z *= w0; ra.w *= w0;
    }
#pragma unroll
    for (int j = 0; j < 4; j++) {
        int idx = tid + j * 256;
        int r = idx >> 6, c4 = (idx & 63) * 4;
        int t = kbeg + r;
        const float* src = (t == spos) ? (kvnew + (long long)b * KVLR + c0 + c4)
                                       : (kvc + ((long long)b * MAXS + t) * KVLR + c0 + c4);
        rb[j] = *(const float4*)src;
    }
    As[akq+0][acol] = f2tf(ra.x); As[akq+1][acol] = f2tf(ra.y);
    As[akq+2][acol] = f2tf(ra.z); As[akq+3][acol] = f2tf(ra.w);
#pragma unroll
    for (int j = 0; j < 4; j++) {
        int idx = tid + j * 256;
        int r = idx >> 6, c4 = (idx & 63) * 4;
        uint4 u = make_uint4(f2tf(rb[j].x), f2tf(rb[j].y), f2tf(rb[j].z), f2tf(rb[j].w));
        *(uint4*)&Bs[r][c4] = u;
    }
    __syncthreads();

    float acc[2][8][4];
#pragma unroll
    for (int mi = 0; mi < 2; mi++)
#pragma unroll
        for (int nj = 0; nj < 8; nj++)
#pragma unroll
            for (int r = 0; r < 4; r++) acc[mi][nj][r] = 0.f;

    for (int k0 = kbeg; k0 < kend; k0 += 16) {
        const bool more = (k0 + 16) < kend;
        if (more) {
            float w0 = ws[ah][(k0 + 16) >> 8];
            ra = *(const float4*)(A + (long long)ah * MAXS + (k0+16) + akq);
            ra.x *= w0; ra.y *= w0; ra.z *= w0; ra.w *= w0;
#pragma unroll
            for (int j = 0; j < 4; j++) {
                int idx = tid + j * 256;
                int r = idx >> 6, c4 = (idx & 63) * 4;
                int t = k0 + 16 + r;
                const float* src = (t == spos) ? (kvnew + (long long)b * KVLR + c0 + c4)
                                               : (kvc + ((long long)b * MAXS + t) * KVLR + c0 + c4);
                rb[j] = *(const float4*)src;
            }
        }
#pragma unroll
        for (int s = 0; s < 2; s++) {
            const int kk = s * 8;
            const int key0 = 8 * ((kk >> 2) & 3);
            const int key1 = 8 * (((kk >> 2) + 1) & 3);
            unsigned af[2][4];
#pragma unroll
            for (int mi = 0; mi < 2; mi++) {
                int r0 = wh + mi*16 + gid;
                af[mi][0] = As[kk+tig  ][ r0    ^ key0];
                af[mi][1] = As[kk+tig  ][(r0+8) ^ key0];
                af[mi][2] = As[kk+tig+4][ r0    ^ key1];
                af[mi][3] = As[kk+tig+4][(r0+8) ^ key1];
            }
            unsigned bf[8][2];
#pragma unroll
            for (int nj = 0; nj < 8; nj++) {
                bf[nj][0] = Bs[kk+tig  ][wc + nj*8 + gid];
                bf[nj][1] = Bs[kk+tig+4][wc + nj*8 + gid];
            }
#pragma unroll
            for (int mi = 0; mi < 2; mi++)
#pragma unroll
                for (int nj = 0; nj < 8; nj++)
                    mma8(acc[mi][nj], af[mi], bf[nj]);
        }
        __syncthreads();
        if (more) {
            As[akq+0][acol] = f2tf(ra.x); As[akq+1][acol] = f2tf(ra.y);
            As[akq+2][acol] = f2tf(ra.z); As[akq+3][acol] = f2tf(ra.w);
#pragma unroll
            for (int j = 0; j < 4; j++) {
                int idx = tid + j * 256;
                int r = idx >> 6, c4 = (idx & 63) * 4;
                uint4 u = make_uint4(f2tf(rb[j].x), f2tf(rb[j].y), f2tf(rb[j].z), f2tf(rb[j].w));
                *(uint4*)&Bs[r][c4] = u;
            }
            __syncthreads();
        }
    }

#pragma unroll
    for (int mi = 0; mi < 2; mi++)
#pragma unroll
        for (int nj = 0; nj < 8; nj++) {
            float* cp = C + (long long)(wh + mi*16 + gid) * KVLR + c0 + wc + nj*8 + 2*tig;
            atomicAdd(cp,            acc[mi][nj][0]);
            atomicAdd(cp + 1,        acc[mi][nj][1]);
            atomicAdd(cp + 8*KVLR,   acc[mi][nj][2]);
            atomicAdd(cp + 8*KVLR+1, acc[mi][nj][3]);
        }
}

// =====================================================================
// FFMA split-K GEMV (kvfull, ohead)
// =====================================================================
template<int BN, int TN>
__global__ void __launch_bounds__(256) gemv_splitk(
    const float* __restrict__ A, const float* __restrict__ B, float* __restrict__ C,
    int N, int lda, int ldb, int ldc, int kChunk,
    long long aB, long long bB, long long cB)
{
    A += (long long)blockIdx.z * aB;
    B += (long long)blockIdx.z * bB;
    C += (long long)blockIdx.z * cB;
    const int n0 = blockIdx.x * BN;
    const int ks = blockIdx.y * kChunk;
    const int ke = ks + kChunk;

    __shared__ __align__(16) ull   As2[16][32];
    __shared__ __align__(16) float Bsf [16][BN];

    const int tid = threadIdx.x;
    const int tx = tid & 31, ty = tid >> 5;

    const bool aon = tid < 128;
    const int am = tid >> 2, akq = (tid & 3) << 2;
    constexpr int PER = BN / 64;
    const int bn  = tid % BN;
    const int bkq = (tid / BN) * PER;
    const bool bon = (n0 + bn) < N;

    float4 ra = make_float4(0,0,0,0);
    float4 rb[PER];
#pragma unroll
    for (int j = 0; j < PER; j++) rb[j] = make_float4(0,0,0,0);

    if (aon) ra = *(const float4*)(A + (long long)am * lda + ks + akq);
    if (bon) {
        const float* bp = B + (long long)(n0 + bn) * ldb + ks + bkq * 4;
#pragma unroll
        for (int j = 0; j < PER; j++) rb[j] = *(const float4*)(bp + j * 4);
    }
    if (aon) {
        As2[akq+0][am] = dup2(ra.x); As2[akq+1][am] = dup2(ra.y);
        As2[akq+2][am] = dup2(ra.z); As2[akq+3][am] = dup2(ra.w);
    }
#pragma unroll
    for (int j = 0; j < PER; j++) {
        Bsf[(bkq+j)*4+0][bn] = rb[j].x;
        Bsf[(bkq+j)*4+1][bn] = rb[j].y;
        Bsf[(bkq+j)*4+2][bn] = rb[j].z;
        Bsf[(bkq+j)*4+3][bn] = rb[j].w;
    }
    __syncthreads();

    ull acc[4][TN/2];
#pragma unroll
    for (int m = 0; m < 4; m++)
#pragma unroll
        for (int j = 0; j < TN/2; j++) acc[m][j] = 0ull;

    for (int k0 = ks; k0 < ke; k0 += 16) {
        const bool more = (k0 + 16) < ke;
        if (more) {
            if (aon) ra = *(const float4*)(A + (long long)am * lda + (k0+16) + akq);
            if (bon) {
                const float* bp = B + (long long)(n0 + bn) * ldb + (k0+16) + bkq * 4;
#pragma unroll
                for (int j = 0; j < PER; j++) rb[j] = *(const float4*)(bp + j * 4);
            }
        }
#pragma unroll
        for (int kk = 0; kk < 16; kk++) {
            ulonglong2 a01 = *(const ulonglong2*)&As2[kk][ty*4];
            ulonglong2 a23 = *(const ulonglong2*)&As2[kk][ty*4+2];
            ull a[4] = {a01.x, a01.y, a23.x, a23.y};
            ull bq[TN/2];
            if constexpr (TN == 8) {
                ulonglong2 b0 = *(const ulonglong2*)&Bsf[kk][tx*8];
                ulonglong2 b1 = *(const ulonglong2*)&Bsf[kk][tx*8+4];
                bq[0]=b0.x; bq[1]=b0.y; bq[2]=b1.x; bq[3]=b1.y;
            } else {
                ulonglong2 b0 = *(const ulonglong2*)&Bsf[kk][tx*4];
                bq[0]=b0.x; bq[1]=b0.y;
            }
#pragma unroll
            for (int m = 0; m < 4; m++)
#pragma unroll
                for (int j = 0; j < TN/2; j++)
                    acc[m][j] = fma2(a[m], bq[j], acc[m][j]);
        }
        __syncthreads();
        if (more) {
            if (aon) {
                As2[akq+0][am] = dup2(ra.x); As2[akq+1][am] = dup2(ra.y);
                As2[akq+2][am] = dup2(ra.z); As2[akq+3][am] = dup2(ra.w);
            }
#pragma unroll
            for (int j = 0; j < PER; j++) {
                Bsf[(bkq+j)*4+0][bn] = rb[j].x;
                Bsf[(bkq+j)*4+1][bn] = rb[j].y;
                Bsf[(bkq+j)*4+2][bn] = rb[j].z;
                Bsf[(bkq+j)*4+3][bn] = rb[j].w;
            }
        }
        __syncthreads();
    }

    const int nb = n0 + tx * TN;
#pragma unroll
    for (int m = 0; m < 4; m++) {
        float* cp = C + (long long)(ty*4+m) * ldc + nb;
#pragma unroll
        for (int j = 0; j < TN/2; j++) {
            float2 f = u2f(acc[m][j]);
            if (nb + 2*j     < N) atomicAdd(cp + 2*j,     f.x);
            if (nb + 2*j + 1 < N) atomicAdd(cp + 2*j + 1, f.y);
        }
    }
}

// ---------------- launch ----------------
extern "C" void kernel_launch(void* const* d_in, const int* in_sizes, int n_in,
                              void* d_out, int out_size)
{
    const float* x        = (const float*)d_in[0];
    const float* fc       = (const float*)d_in[1];
    const float* fs       = (const float*)d_in[2];
    const float* kvc      = (const float*)d_in[3];
    const float* pec      = (const float*)d_in[4];
    const float* wq_a     = (const float*)d_in[5];
    const float* q_norm_w = (const float*)d_in[6];
    const float* wq_b     = (const float*)d_in[7];
    const float* wkv_a    = (const float*)d_in[8];
    const float* kv_norm  = (const float*)d_in[9];
    const float* wkv_b    = (const float*)d_in[10];
    const float* wo       = (const float*)d_in[11];
    const int*   spos     = (const int*)d_in[12];
    float*       out      = (float*)d_out;

    float *qlat, *kvfull, *kvnew, *penew, *q, *qcat, *scores, *ml, *wv, *olat, *ohead;
    cudaGetSymbolAddress((void**)&qlat,   g_qlat);
    cudaGetSymbolAddress((void**)&kvfull, g_kvfull);
    cudaGetSymbolAddress((void**)&kvnew,  g_kvnew);
    cudaGetSymbolAddress((void**)&penew,  g_penew);
    cudaGetSymbolAddress((void**)&q,      g_q);
    cudaGetSymbolAddress((void**)&qcat,   g_qcat);
    cudaGetSymbolAddress((void**)&scores, g_scores);
    cudaGetSymbolAddress((void**)&ml,     g_ml);
    cudaGetSymbolAddress((void**)&wv,     g_w);
    cudaGetSymbolAddress((void**)&olat,   g_olat);
    cudaGetSymbolAddress((void**)&ohead,  g_ohead);

    cudaMemsetAsync(qlat,   0, (size_t)BATCH * QLR  * 4);
    cudaMemsetAsync(kvfull, 0, (size_t)BATCH * KCAT * 4);
    cudaMemsetAsync(q,      0, (size_t)BATCH * QDIM * 4);
    cudaMemsetAsync(olat,   0, (size_t)BATCH * H * KVLR * 4);
    cudaMemsetAsync(ohead,  0, (size_t)BATCH * ODIM * 4);
    cudaMemsetAsync(out,    0, (size_t)out_size * 4);

    dim3 blk(256);

    // q_lat = x @ wq_a^T   (N=1536, K=7168)
    gemv_mma<<<dim3(6,16,1), blk>>>(x, wq_a, qlat, DIM, DIM, QLR, 448);
    // kv_full = x @ wkv_a^T (N=576, K=7168)
    gemv_splitk<256,8><<<dim3(3,32,1), blk>>>(x, wkv_a, kvfull, KCAT, DIM, DIM, KCAT, 224, 0,0,0);
    rmsnorm_kernel<<<32, 256>>>(qlat, q_norm_w, QLR);
    kvprep_kernel<<<32, 256>>>(kvfull, kv_norm, fc, fs, kvnew, penew);
    // q = q_lat @ wq_b^T   (N=24576, K=1536)
    gemv_mma<<<dim3(96,3,1), blk>>>(qlat, wq_b, q, QLR, QLR, QDIM, 512);
    qrope_kernel<<<512, 256>>>(q, fc, fs, qcat);
    qabs_kernel<<<128, 512>>>(q, wkv_b, qcat);
    // scores + block-local softmax
    scores_sm<<<dim3(MAXS/256, H/64, BATCH), blk>>>(
        qcat, kvc, pec, kvnew, penew, scores, (float2*)ml, spos);
    // block weights
    wcomb_kernel<<<(BATCH*H + 255)/256, 256>>>((const float2*)ml, wv);
    // weighted olat
    olat_w<<<dim3(KVLR/256, 4, BATCH), blk>>>(scores, kvc, kvnew, wv, olat, spos);
    // ohead per head
    gemv_splitk<128,4><<<dim3(1,1,H), blk>>>(olat, wkv_b + 128*KVLR, ohead,
                                             DV, H*KVLR, KVLR, ODIM, KVLR,
                                             (long long)KVLR, (long long)256*KVLR, (long long)DV);
    // out = ohead @ wo^T   (N=7168, K=16384)
    gemv_mma<<<dim3(28,8,1), blk>>>(ohead, wo, out, ODIM, ODIM, DIM, 2048);
}

// round 8
// speedup vs baseline: 1.6616x; 1.1081x over previous
#include <cuda_runtime.h>
#include <cuda_bf16.h>

// ---------------- problem constants ----------------
#define BATCH 32
#define DIM   7168
#define H     128
#define QLR   1536
#define KVLR  512
#define DN    128
#define DR    64
#define DV    128
#define QKD   192
#define MAXS  4096
#define QDIM  (H*QKD)      // 24576
#define KCAT  (KVLR+DR)    // 576
#define ODIM  (H*DV)       // 16384
#define NBLK  (MAXS/256)   // 16 t-blocks

#define SCALE_F 0.07216878364870322f
#define EPS_F   1e-6f

typedef unsigned long long ull;

// ---------------- helpers ----------------
__device__ __forceinline__ ull fma2(ull a, ull b, ull c) {
    ull d;
    asm("fma.rn.f32x2 %0, %1, %2, %3;" : "=l"(d) : "l"(a), "l"(b), "l"(c));
    return d;
}
__device__ __forceinline__ ull dup2(float x) {
    ull d;
    asm("mov.b64 %0, {%1, %1};" : "=l"(d) : "f"(x));
    return d;
}
__device__ __forceinline__ float2 u2f(ull v) {
    float2 f;
    f.x = __uint_as_float((unsigned)(v & 0xffffffffull));
    f.y = __uint_as_float((unsigned)(v >> 32));
    return f;
}
__device__ __forceinline__ unsigned f2tf(float f) {
    unsigned u; asm("cvt.rna.tf32.f32 %0, %1;" : "=r"(u) : "f"(f)); return u;
}
__device__ __forceinline__ void mma8(float* c, const unsigned* a, const unsigned* b) {
    asm volatile("mma.sync.aligned.m16n8k8.row.col.f32.tf32.tf32.f32 "
                 "{%0,%1,%2,%3}, {%4,%5,%6,%7}, {%8,%9}, {%0,%1,%2,%3};"
                 : "+f"(c[0]), "+f"(c[1]), "+f"(c[2]), "+f"(c[3])
                 : "r"(a[0]), "r"(a[1]), "r"(a[2]), "r"(a[3]),
                   "r"(b[0]), "r"(b[1]));
}

// ---------------- scratch ----------------
__device__ __align__(16) float g_qlat  [BATCH * QLR];
__device__ __align__(16) float g_kvfull[BATCH * KCAT];
__device__ __align__(16) float g_kvnew [BATCH * KVLR];
__device__ __align__(16) float g_penew [BATCH * DR];
__device__ __align__(16) float g_q     [BATCH * QDIM];
__device__ __align__(16) float g_qcat  [BATCH * H * KCAT];
__device__ __align__(16) float g_scores[(long long)BATCH * H * MAXS];
__device__ __align__(16) float g_ml    [BATCH * H * NBLK * 2];
__device__ __align__(16) float g_w     [BATCH * H * NBLK];
__device__ __align__(16) float g_olat  [BATCH * H * KVLR];
__device__ __align__(16) float g_ohead [BATCH * ODIM];

// ---------------- reductions ----------------
__device__ __forceinline__ float warpSum(float v) {
#pragma unroll
    for (int o = 16; o; o >>= 1) v += __shfl_xor_sync(0xffffffffu, v, o);
    return v;
}
__device__ __forceinline__ float blockSum256(float v) {
    __shared__ float sm[8];
    int lane = threadIdx.x & 31, w = threadIdx.x >> 5;
    __syncthreads();
    v = warpSum(v);
    if (!lane) sm[w] = v;
    __syncthreads();
    float r = 0.f;
#pragma unroll
    for (int i = 0; i < 8; i++) r += sm[i];
    return r;
}

// =====================================================================
// TF32 MMA split-K GEMV, double-buffered smem (1 sync / 16-k iter)
// C[32, N] += A[32,K(chunk)] * B[N,K]^T (atomic)
// =====================================================================
__global__ void __launch_bounds__(256) gemv_mma(
    const float* __restrict__ A, const float* __restrict__ B, float* __restrict__ C,
    int lda, int ldb, int ldc, int kChunk)
{
    const int n0 = blockIdx.x * 256;
    const int ks = blockIdx.y * kChunk;
    const int nIter = kChunk / 16;

    __shared__ unsigned As[2][16][40];
    __shared__ unsigned Bs[2][16][264];

    const int tid = threadIdx.x, lane = tid & 31, wid = tid >> 5;
    const int gid = lane >> 2, tig = lane & 3;
    const int wn = wid * 32;

    const bool aon = tid < 128;
    const int am = tid >> 2, akq = (tid & 3) * 4;
    const int acol = am ^ (8 * ((akq >> 2) & 3));
    const long long brow = (long long)(n0 + tid) * ldb;

    float4 ra = make_float4(0,0,0,0);
    float4 rb[4];

    // prologue -> buffer 0
    if (aon) ra = *(const float4*)(A + (long long)am * lda + ks + akq);
#pragma unroll
    for (int j = 0; j < 4; j++) rb[j] = *(const float4*)(B + brow + ks + j*4);
    if (aon) {
        As[0][akq+0][acol] = f2tf(ra.x); As[0][akq+1][acol] = f2tf(ra.y);
        As[0][akq+2][acol] = f2tf(ra.z); As[0][akq+3][acol] = f2tf(ra.w);
    }
#pragma unroll
    for (int j = 0; j < 4; j++) {
        Bs[0][j*4+0][tid] = f2tf(rb[j].x); Bs[0][j*4+1][tid] = f2tf(rb[j].y);
        Bs[0][j*4+2][tid] = f2tf(rb[j].z); Bs[0][j*4+3][tid] = f2tf(rb[j].w);
    }
    __syncthreads();

    float acc[2][4][4];
#pragma unroll
    for (int mi = 0; mi < 2; mi++)
#pragma unroll
        for (int nj = 0; nj < 4; nj++)
#pragma unroll
            for (int r = 0; r < 4; r++) acc[mi][nj][r] = 0.f;

    for (int it = 0; it < nIter; it++) {
        const int cur = it & 1, nxt = cur ^ 1;
        const bool more = (it + 1) < nIter;
        const int k1 = ks + (it + 1) * 16;
        if (more) {
            if (aon) ra = *(const float4*)(A + (long long)am * lda + k1 + akq);
#pragma unroll
            for (int j = 0; j < 4; j++) rb[j] = *(const float4*)(B + brow + k1 + j*4);
        }
#pragma unroll
        for (int s = 0; s < 2; s++) {
            const int kk = s * 8;
            const int key0 = 8 * ((kk >> 2) & 3);
            const int key1 = 8 * (((kk >> 2) + 1) & 3);
            unsigned af[2][4];
#pragma unroll
            for (int mi = 0; mi < 2; mi++) {
                int r0 = mi*16 + gid;
                af[mi][0] = As[cur][kk+tig  ][ r0    ^ key0];
                af[mi][1] = As[cur][kk+tig  ][(r0+8) ^ key0];
                af[mi][2] = As[cur][kk+tig+4][ r0    ^ key1];
                af[mi][3] = As[cur][kk+tig+4][(r0+8) ^ key1];
            }
            unsigned bf[4][2];
#pragma unroll
            for (int nj = 0; nj < 4; nj++) {
                bf[nj][0] = Bs[cur][kk+tig  ][wn + nj*8 + gid];
                bf[nj][1] = Bs[cur][kk+tig+4][wn + nj*8 + gid];
            }
#pragma unroll
            for (int mi = 0; mi < 2; mi++)
#pragma unroll
                for (int nj = 0; nj < 4; nj++)
                    mma8(acc[mi][nj], af[mi], bf[nj]);
        }
        if (more) {
            if (aon) {
                As[nxt][akq+0][acol] = f2tf(ra.x); As[nxt][akq+1][acol] = f2tf(ra.y);
                As[nxt][akq+2][acol] = f2tf(ra.z); As[nxt][akq+3][acol] = f2tf(ra.w);
            }
#pragma unroll
            for (int j = 0; j < 4; j++) {
                Bs[nxt][j*4+0][tid] = f2tf(rb[j].x); Bs[nxt][j*4+1][tid] = f2tf(rb[j].y);
                Bs[nxt][j*4+2][tid] = f2tf(rb[j].z); Bs[nxt][j*4+3][tid] = f2tf(rb[j].w);
            }
        }
        __syncthreads();
    }

#pragma unroll
    for (int mi = 0; mi < 2; mi++)
#pragma unroll
        for (int nj = 0; nj < 4; nj++) {
            float* cp = C + (long long)(mi*16+gid)*ldc + n0 + wn + nj*8 + 2*tig;
            atomicAdd(cp,           acc[mi][nj][0]);
            atomicAdd(cp + 1,       acc[mi][nj][1]);
            atomicAdd(cp + 8*ldc,   acc[mi][nj][2]);
            atomicAdd(cp + 8*ldc+1, acc[mi][nj][3]);
        }
}

// ---------------- rmsnorm (in place) ----------------
__global__ void __launch_bounds__(256) rmsnorm_kernel(float* __restrict__ v,
                                                      const float* __restrict__ w, int n)
{
    int b = blockIdx.x;
    float* row = v + (long long)b * n;
    float ss = 0.f;
    for (int i = threadIdx.x; i < n; i += 256) { float x = row[i]; ss += x * x; }
    ss = blockSum256(ss);
    __shared__ float s_scale;
    if (threadIdx.x == 0) s_scale = rsqrtf(ss / (float)n + EPS_F);
    __syncthreads();
    float sc = s_scale;
    for (int i = threadIdx.x; i < n; i += 256) row[i] = row[i] * sc * w[i];
}

// ---------------- kv prep ----------------
__global__ void __launch_bounds__(256) kvprep_kernel(
    const float* __restrict__ kvfull, const float* __restrict__ w,
    const float* __restrict__ fc, const float* __restrict__ fs,
    float* __restrict__ kvnew, float* __restrict__ penew)
{
    int b = blockIdx.x;
    const float* row = kvfull + (long long)b * KCAT;
    float ss = 0.f;
    for (int i = threadIdx.x; i < KVLR; i += 256) { float x = row[i]; ss += x * x; }
    ss = blockSum256(ss);
    __shared__ float s_scale;
    if (threadIdx.x == 0) s_scale = rsqrtf(ss / (float)KVLR + EPS_F);
    __syncthreads();
    float sc = s_scale;
    for (int i = threadIdx.x; i < KVLR; i += 256)
        kvnew[(long long)b * KVLR + i] = row[i] * sc * w[i];
    if (threadIdx.x < 32) {
        int i = threadIdx.x;
        float x1 = row[KVLR + 2 * i], x2 = row[KVLR + 2 * i + 1];
        float c = fc[i], s = fs[i];
        penew[(long long)b * DR + 2 * i]     = x1 * c - x2 * s;
        penew[(long long)b * DR + 2 * i + 1] = x1 * s + x2 * c;
    }
}

// ---------------- q rope -> qcat tail (scaled) ----------------
__global__ void __launch_bounds__(256) qrope_kernel(
    const float* __restrict__ q, const float* __restrict__ fc,
    const float* __restrict__ fs, float* __restrict__ qcat)
{
    int idx = blockIdx.x * 256 + threadIdx.x;
    if (idx >= BATCH * H * (DR / 2)) return;
    int i  = idx & 31;
    int bh = idx >> 5;
    int b  = bh >> 7, h = bh & 127;
    const float* src = q + (long long)b * QDIM + h * QKD + DN;
    float x1 = src[2 * i], x2 = src[2 * i + 1];
    float c = fc[i], s = fs[i];
    qcat[(long long)bh * KCAT + KVLR + 2 * i]     = (x1 * c - x2 * s) * SCALE_F;
    qcat[(long long)bh * KCAT + KVLR + 2 * i + 1] = (x1 * s + x2 * c) * SCALE_F;
}

// ---------------- q_abs (FFMA, small) ----------------
__global__ void __launch_bounds__(512) qabs_kernel(
    const float* __restrict__ q, const float* __restrict__ wkvb, float* __restrict__ qcat)
{
    int h = blockIdx.x;
    __shared__ __align__(16) float sq[DN][BATCH];
    int tid = threadIdx.x;
#pragma unroll
    for (int i = 0; i < 8; i++) {
        int idx = tid + i * 512;
        int d = idx >> 5, b = idx & 31;
        sq[d][b] = q[(long long)b * QDIM + h * QKD + d];
    }
    __syncthreads();
    int c = tid;
    ull acc[16];
#pragma unroll
    for (int i = 0; i < 16; i++) acc[i] = 0ull;
    const float* w = wkvb + (long long)h * 256 * KVLR + c;
#pragma unroll 4
    for (int d = 0; d < DN; d++) {
        ull w2 = dup2(w[(long long)d * KVLR]);
#pragma unroll
        for (int bp = 0; bp < 16; bp++) {
            ull qp = *(const ull*)&sq[d][bp * 2];
            acc[bp] = fma2(qp, w2, acc[bp]);
        }
    }
#pragma unroll
    for (int bp = 0; bp < 16; bp++) {
        float2 f = u2f(acc[bp]);
        qcat[((long long)(2 * bp + 0) * H + h) * KCAT + c] = f.x * SCALE_F;
        qcat[((long long)(2 * bp + 1) * H + h) * KCAT + c] = f.y * SCALE_F;
    }
}

// ---------------- KV row loader ----------------
__device__ __forceinline__ void load_kvrow16(float4* rb,
        const float* __restrict__ kvc, const float* __restrict__ pec,
        const float* __restrict__ kvnew, const float* __restrict__ penew,
        int b, int t, int spos, int k0)
{
    const float* src;
    if (k0 < KVLR)
        src = (t == spos) ? (kvnew + (long long)b * KVLR + k0)
                          : (kvc + ((long long)b * MAXS + t) * KVLR + k0);
    else
        src = (t == spos) ? (penew + (long long)b * DR + (k0 - KVLR))
                          : (pec + ((long long)b * MAXS + t) * DR + (k0 - KVLR));
#pragma unroll
    for (int j = 0; j < 4; j++) rb[j] = *(const float4*)(src + j * 4);
}

// =====================================================================
// scores + block-local softmax, double-buffered: writes P' and (m,l)
// tile 64h x 256t, warps 2x4 (32h x 64t each)
// =====================================================================
__global__ void __launch_bounds__(256) scores_sm(
    const float* __restrict__ qcat, const float* __restrict__ kvc, const float* __restrict__ pec,
    const float* __restrict__ kvnew, const float* __restrict__ penew,
    float* __restrict__ S, float2* __restrict__ mlv, const int* __restrict__ spos_p)
{
    const int b = blockIdx.z, spos = *spos_p;
    const int t0 = blockIdx.x * 256, h0 = blockIdx.y * 64;
    const float* A = qcat + ((long long)b * H + h0) * KCAT;
    float* C = S + ((long long)b * H + h0) * MAXS;

    __shared__ unsigned As[2][16][72];
    __shared__ unsigned Bs[2][16][264];
    __shared__ float red[64][4];

    const int tid = threadIdx.x, lane = tid & 31, wid = tid >> 5;
    const int gid = lane >> 2, tig = lane & 3;
    const int wh = (wid & 1) * 32, wt = (wid >> 1) * 64;
    const int wtq = wid >> 1;

    const int ah = tid >> 2, akq = (tid & 3) * 4;
    const int acol = ah ^ (8 * ((akq >> 2) & 3));
    const int bt = t0 + tid;

    float4 ra; float4 rb[4];
    ra = *(const float4*)(A + (long long)ah * KCAT + akq);
    load_kvrow16(rb, kvc, pec, kvnew, penew, b, bt, spos, 0);
    As[0][akq+0][acol] = f2tf(ra.x); As[0][akq+1][acol] = f2tf(ra.y);
    As[0][akq+2][acol] = f2tf(ra.z); As[0][akq+3][acol] = f2tf(ra.w);
#pragma unroll
    for (int j = 0; j < 4; j++) {
        Bs[0][j*4+0][tid] = f2tf(rb[j].x); Bs[0][j*4+1][tid] = f2tf(rb[j].y);
        Bs[0][j*4+2][tid] = f2tf(rb[j].z); Bs[0][j*4+3][tid] = f2tf(rb[j].w);
    }
    __syncthreads();

    float acc[2][8][4];
#pragma unroll
    for (int mi = 0; mi < 2; mi++)
#pragma unroll
        for (int nj = 0; nj < 8; nj++)
#pragma unroll
            for (int r = 0; r < 4; r++) acc[mi][nj][r] = 0.f;

    for (int it = 0; it < KCAT / 16; it++) {
        const int cur = it & 1, nxt = cur ^ 1;
        const bool more = (it + 1) < KCAT / 16;
        const int k1 = (it + 1) * 16;
        if (more) {
            ra = *(const float4*)(A + (long long)ah * KCAT + k1 + akq);
            load_kvrow16(rb, kvc, pec, kvnew, penew, b, bt, spos, k1);
        }
#pragma unroll
        for (int s = 0; s < 2; s++) {
            const int kk = s * 8;
            const int key0 = 8 * ((kk >> 2) & 3);
            const int key1 = 8 * (((kk >> 2) + 1) & 3);
            unsigned af[2][4];
#pragma unroll
            for (int mi = 0; mi < 2; mi++) {
                int r0 = wh + mi*16 + gid;
                af[mi][0] = As[cur][kk+tig  ][ r0    ^ key0];
                af[mi][1] = As[cur][kk+tig  ][(r0+8) ^ key0];
                af[mi][2] = As[cur][kk+tig+4][ r0    ^ key1];
                af[mi][3] = As[cur][kk+tig+4][(r0+8) ^ key1];
            }
            unsigned bf[8][2];
#pragma unroll
            for (int nj = 0; nj < 8; nj++) {
                bf[nj][0] = Bs[cur][kk+tig  ][wt + nj*8 + gid];
                bf[nj][1] = Bs[cur][kk+tig+4][wt + nj*8 + gid];
            }
#pragma unroll
            for (int mi = 0; mi < 2; mi++)
#pragma unroll
                for (int nj = 0; nj < 8; nj++)
                    mma8(acc[mi][nj], af[mi], bf[nj]);
        }
        if (more) {
            As[nxt][akq+0][acol] = f2tf(ra.x); As[nxt][akq+1][acol] = f2tf(ra.y);
            As[nxt][akq+2][acol] = f2tf(ra.z); As[nxt][akq+3][acol] = f2tf(ra.w);
#pragma unroll
            for (int j = 0; j < 4; j++) {
                Bs[nxt][j*4+0][tid] = f2tf(rb[j].x); Bs[nxt][j*4+1][tid] = f2tf(rb[j].y);
                Bs[nxt][j*4+2][tid] = f2tf(rb[j].z); Bs[nxt][j*4+3][tid] = f2tf(rb[j].w);
            }
        }
        __syncthreads();
    }

    // ---------------- block-local softmax epilogue ----------------
    float m_lo[2], m_hi[2];
#pragma unroll
    for (int mi = 0; mi < 2; mi++) {
        float a = -1e30f, c = -1e30f;
#pragma unroll
        for (int nj = 0; nj < 8; nj++) {
            int t = t0 + wt + nj*8 + 2*tig;
            float v0 = (t     <= spos) ? acc[mi][nj][0] : -1e30f;
            float v1 = (t + 1 <= spos) ? acc[mi][nj][1] : -1e30f;
            float v2 = (t     <= spos) ? acc[mi][nj][2] : -1e30f;
            float v3 = (t + 1 <= spos) ? acc[mi][nj][3] : -1e30f;
            a = fmaxf(a, fmaxf(v0, v1));
            c = fmaxf(c, fmaxf(v2, v3));
        }
        a = fmaxf(a, __shfl_xor_sync(0xffffffffu, a, 1));
        a = fmaxf(a, __shfl_xor_sync(0xffffffffu, a, 2));
        c = fmaxf(c, __shfl_xor_sync(0xffffffffu, c, 1));
        c = fmaxf(c, __shfl_xor_sync(0xffffffffu, c, 2));
        m_lo[mi] = a; m_hi[mi] = c;
    }
    if (tig == 0) {
#pragma unroll
        for (int mi = 0; mi < 2; mi++) {
            red[wh + mi*16 + gid    ][wtq] = m_lo[mi];
            red[wh + mi*16 + gid + 8][wtq] = m_hi[mi];
        }
    }
    __syncthreads();
#pragma unroll
    for (int mi = 0; mi < 2; mi++) {
        int r = wh + mi*16 + gid;
        m_lo[mi] = fmaxf(fmaxf(red[r][0],   red[r][1]),   fmaxf(red[r][2],   red[r][3]));
        m_hi[mi] = fmaxf(fmaxf(red[r+8][0], red[r+8][1]), fmaxf(red[r+8][2], red[r+8][3]));
    }
    __syncthreads();
    float s_lo[2] = {0.f, 0.f}, s_hi[2] = {0.f, 0.f};
#pragma unroll
    for (int mi = 0; mi < 2; mi++) {
#pragma unroll
        for (int nj = 0; nj < 8; nj++) {
            int t = t0 + wt + nj*8 + 2*tig;
            float e0 = (t     <= spos) ? __expf(acc[mi][nj][0] - m_lo[mi]) : 0.f;
            float e1 = (t + 1 <= spos) ? __expf(acc[mi][nj][1] - m_lo[mi]) : 0.f;
            float e2 = (t     <= spos) ? __expf(acc[mi][nj][2] - m_hi[mi]) : 0.f;
            float e3 = (t + 1 <= spos) ? __expf(acc[mi][nj][3] - m_hi[mi]) : 0.f;
            acc[mi][nj][0] = e0; acc[mi][nj][1] = e1;
            acc[mi][nj][2] = e2; acc[mi][nj][3] = e3;
            s_lo[mi] += e0 + e1; s_hi[mi] += e2 + e3;
        }
        s_lo[mi] += __shfl_xor_sync(0xffffffffu, s_lo[mi], 1);
        s_lo[mi] += __shfl_xor_sync(0xffffffffu, s_lo[mi], 2);
        s_hi[mi] += __shfl_xor_sync(0xffffffffu, s_hi[mi], 1);
        s_hi[mi] += __shfl_xor_sync(0xffffffffu, s_hi[mi], 2);
    }
    if (tig == 0) {
#pragma unroll
        for (int mi = 0; mi < 2; mi++) {
            red[wh + mi*16 + gid    ][wtq] = s_lo[mi];
            red[wh + mi*16 + gid + 8][wtq] = s_hi[mi];
        }
    }
    __syncthreads();
    if (wtq == 0 && tig == 0) {
#pragma unroll
        for (int mi = 0; mi < 2; mi++) {
            int r = wh + mi*16 + gid;
            float l0 = red[r][0]   + red[r][1]   + red[r][2]   + red[r][3];
            float l1 = red[r+8][0] + red[r+8][1] + red[r+8][2] + red[r+8][3];
            mlv[((long long)(b * H + h0 + r))     * NBLK + blockIdx.x] = make_float2(m_lo[mi], l0);
            mlv[((long long)(b * H + h0 + r + 8)) * NBLK + blockIdx.x] = make_float2(m_hi[mi], l1);
        }
    }

    // write P'
#pragma unroll
    for (int mi = 0; mi < 2; mi++)
#pragma unroll
        for (int nj = 0; nj < 8; nj++) {
            float* cp = C + (long long)(wh + mi*16 + gid) * MAXS + t0 + wt + nj*8 + 2*tig;
            *(float2*)cp            = make_float2(acc[mi][nj][0], acc[mi][nj][1]);
            *(float2*)(cp + 8*MAXS) = make_float2(acc[mi][nj][2], acc[mi][nj][3]);
        }
}

// ---------------- combine weights: w[row][blk] = exp(m_blk - M)/L ----------------
__global__ void __launch_bounds__(256) wcomb_kernel(
    const float2* __restrict__ mlv, float* __restrict__ wv)
{
    int row = blockIdx.x * 256 + threadIdx.x;
    if (row >= BATCH * H) return;
    const float2* p = mlv + (long long)row * NBLK;
    float2 v[NBLK];
    float M = -1e30f;
#pragma unroll
    for (int i = 0; i < NBLK; i++) { v[i] = p[i]; M = fmaxf(M, v[i].x); }
    float L = 0.f;
#pragma unroll
    for (int i = 0; i < NBLK; i++) L += __expf(v[i].x - M) * v[i].y;
    float inv = 1.f / L;
#pragma unroll
    for (int i = 0; i < NBLK; i++)
        wv[(long long)row * NBLK + i] = __expf(v[i].x - M) * inv;
}

// =====================================================================
// olat: O[b,h,c] = sum_blk w[h][blk] sum_t P'[h,t] kv[t,c]
// tile 64h x 256c, warps 2x4 (32h x 64c), split-k over t (4), atomicAdd
// double-buffered smem
// =====================================================================
__global__ void __launch_bounds__(256) olat_w(
    const float* __restrict__ P, const float* __restrict__ kvc,
    const float* __restrict__ kvnew, const float* __restrict__ wv,
    float* __restrict__ O, const int* __restrict__ spos_p)
{
    const int b = blockIdx.z, spos = *spos_p;
    const int c0 = blockIdx.x * 256;
    const int hb = blockIdx.y >> 2, ks = blockIdx.y & 3;
    const int h0 = hb * 64;
    const float* A = P + ((long long)b * H + h0) * MAXS;
    float* C = O + ((long long)b * H + h0) * KVLR;

    __shared__ unsigned As[2][16][72];
    __shared__ unsigned Bs[2][16][264];
    __shared__ float ws[64][16];

    const int tid = threadIdx.x, lane = tid & 31, wid = tid >> 5;
    const int gid = lane >> 2, tig = lane & 3;
    const int wh = (wid & 1) * 32, wc = (wid >> 1) * 64;

#pragma unroll
    for (int j = 0; j < 4; j++) {
        int idx = tid * 4 + j;
        int r = idx >> 4, blk = idx & 15;
        ws[r][blk] = wv[((long long)(b * H + h0 + r)) * NBLK + blk];
    }
    __syncthreads();

    const int ah = tid >> 2, akq = (tid & 3) * 4;
    const int acol = ah ^ (8 * ((akq >> 2) & 3));
    const int kbeg = ks * (MAXS/4);
    const int nIter = (MAXS/4) / 16;

    float4 ra; float4 rb[4];
    {
        float w0 = ws[ah][kbeg >> 8];
        ra = *(const float4*)(A + (long long)ah * MAXS + kbeg + akq);
        ra.x *= w0; ra.y *= w0; ra.z *= w0; ra.w *= w0;
    }
#pragma unroll
    for (int j = 0; j < 4; j++) {
        int idx = tid + j * 256;
        int r = idx >> 6, c4 = (idx & 63) * 4;
        int t = kbeg + r;
        const float* src = (t == spos) ? (kvnew + (long long)b * KVLR + c0 + c4)
                                       : (kvc + ((long long)b * MAXS + t) * KVLR + c0 + c4);
        rb[j] = *(const float4*)src;
    }
    As[0][akq+0][acol] = f2tf(ra.x); As[0][akq+1][acol] = f2tf(ra.y);
    As[0][akq+2][acol] = f2tf(ra.z); As[0][akq+3][acol] = f2tf(ra.w);
#pragma unroll
    for (int j = 0; j < 4; j++) {
        int idx = tid + j * 256;
        int r = idx >> 6, c4 = (idx & 63) * 4;
        uint4 u = make_uint4(f2tf(rb[j].x), f2tf(rb[j].y), f2tf(rb[j].z), f2tf(rb[j].w));
        *(uint4*)&Bs[0][r][c4] = u;
    }
    __syncthreads();

    float acc[2][8][4];
#pragma unroll
    for (int mi = 0; mi < 2; mi++)
#pragma unroll
        for (int nj = 0; nj < 8; nj++)
#pragma unroll
            for (int r = 0; r < 4; r++) acc[mi][nj][r] = 0.f;

    for (int it = 0; it < nIter; it++) {
        const int cur = it & 1, nxt = cur ^ 1;
        const bool more = (it + 1) < nIter;
        const int k1 = kbeg + (it + 1) * 16;
        if (more) {
            float w0 = ws[ah][k1 >> 8];
            ra = *(const float4*)(A + (long long)ah * MAXS + k1 + akq);
            ra.x *= w0; ra.y *= w0; ra.z *= w0; ra.w *= w0;
#pragma unroll
            for (int j = 0; j < 4; j++) {
                int idx = tid + j * 256;
                int r = idx >> 6, c4 = (idx & 63) * 4;
                int t = k1 + r;
                const float* src = (t == spos) ? (kvnew + (long long)b * KVLR + c0 + c4)
                                               : (kvc + ((long long)b * MAXS + t) * KVLR + c0 + c4);
                rb[j] = *(const float4*)src;
            }
        }
#pragma unroll
        for (int s = 0; s < 2; s++) {
            const int kk = s * 8;
            const int key0 = 8 * ((kk >> 2) & 3);
            const int key1 = 8 * (((kk >> 2) + 1) & 3);
            unsigned af[2][4];
#pragma unroll
            for (int mi = 0; mi < 2; mi++) {
                int r0 = wh + mi*16 + gid;
                af[mi][0] = As[cur][kk+tig  ][ r0    ^ key0];
                af[mi][1] = As[cur][kk+tig  ][(r0+8) ^ key0];
                af[mi][2] = As[cur][kk+tig+4][ r0    ^ key1];
                af[mi][3] = As[cur][kk+tig+4][(r0+8) ^ key1];
            }
            unsigned bf[8][2];
#pragma unroll
            for (int nj = 0; nj < 8; nj++) {
                bf[nj][0] = Bs[cur][kk+tig  ][wc + nj*8 + gid];
                bf[nj][1] = Bs[cur][kk+tig+4][wc + nj*8 + gid];
            }
#pragma unroll
            for (int mi = 0; mi < 2; mi++)
#pragma unroll
                for (int nj = 0; nj < 8; nj++)
                    mma8(acc[mi][nj], af[mi], bf[nj]);
        }
        if (more) {
            As[nxt][akq+0][acol] = f2tf(ra.x); As[nxt][akq+1][acol] = f2tf(ra.y);
            As[nxt][akq+2][acol] = f2tf(ra.z); As[nxt][akq+3][acol] = f2tf(ra.w);
#pragma unroll
            for (int j = 0; j < 4; j++) {
                int idx = tid + j * 256;
                int r = idx >> 6, c4 = (idx & 63) * 4;
                uint4 u = make_uint4(f2tf(rb[j].x), f2tf(rb[j].y), f2tf(rb[j].z), f2tf(rb[j].w));
                *(uint4*)&Bs[nxt][r][c4] = u;
            }
        }
        __syncthreads();
    }

#pragma unroll
    for (int mi = 0; mi < 2; mi++)
#pragma unroll
        for (int nj = 0; nj < 8; nj++) {
            float* cp = C + (long long)(wh + mi*16 + gid) * KVLR + c0 + wc + nj*8 + 2*tig;
            atomicAdd(cp,            acc[mi][nj][0]);
            atomicAdd(cp + 1,        acc[mi][nj][1]);
            atomicAdd(cp + 8*KVLR,   acc[mi][nj][2]);
            atomicAdd(cp + 8*KVLR+1, acc[mi][nj][3]);
        }
}

// =====================================================================
// FFMA split-K GEMV (kvfull, ohead)
// =====================================================================
template<int BN, int TN>
__global__ void __launch_bounds__(256) gemv_splitk(
    const float* __restrict__ A, const float* __restrict__ B, float* __restrict__ C,
    int N, int lda, int ldb, int ldc, int kChunk,
    long long aB, long long bB, long long cB)
{
    A += (long long)blockIdx.z * aB;
    B += (long long)blockIdx.z * bB;
    C += (long long)blockIdx.z * cB;
    const int n0 = blockIdx.x * BN;
    const int ks = blockIdx.y * kChunk;
    const int ke = ks + kChunk;

    __shared__ __align__(16) ull   As2[16][32];
    __shared__ __align__(16) float Bsf [16][BN];

    const int tid = threadIdx.x;
    const int tx = tid & 31, ty = tid >> 5;

    const bool aon = tid < 128;
    const int am = tid >> 2, akq = (tid & 3) << 2;
    constexpr int PER = BN / 64;
    const int bn  = tid % BN;
    const int bkq = (tid / BN) * PER;
    const bool bon = (n0 + bn) < N;

    float4 ra = make_float4(0,0,0,0);
    float4 rb[PER];
#pragma unroll
    for (int j = 0; j < PER; j++) rb[j] = make_float4(0,0,0,0);

    if (aon) ra = *(const float4*)(A + (long long)am * lda + ks + akq);
    if (bon) {
        const float* bp = B + (long long)(n0 + bn) * ldb + ks + bkq * 4;
#pragma unroll
        for (int j = 0; j < PER; j++) rb[j] = *(const float4*)(bp + j * 4);
    }
    if (aon) {
        As2[akq+0][am] = dup2(ra.x); As2[akq+1][am] = dup2(ra.y);
        As2[akq+2][am] = dup2(ra.z); As2[akq+3][am] = dup2(ra.w);
    }
#pragma unroll
    for (int j = 0; j < PER; j++) {
        Bsf[(bkq+j)*4+0][bn] = rb[j].x;
        Bsf[(bkq+j)*4+1][bn] = rb[j].y;
        Bsf[(bkq+j)*4+2][bn] = rb[j].z;
        Bsf[(bkq+j)*4+3][bn] = rb[j].w;
    }
    __syncthreads();

    ull acc[4][TN/2];
#pragma unroll
    for (int m = 0; m < 4; m++)
#pragma unroll
        for (int j = 0; j < TN/2; j++) acc[m][j] = 0ull;

    for (int k0 = ks; k0 < ke; k0 += 16) {
        const bool more = (k0 + 16) < ke;
        if (more) {
            if (aon) ra = *(const float4*)(A + (long long)am * lda + (k0+16) + akq);
            if (bon) {
                const float* bp = B + (long long)(n0 + bn) * ldb + (k0+16) + bkq * 4;
#pragma unroll
                for (int j = 0; j < PER; j++) rb[j] = *(const float4*)(bp + j * 4);
            }
        }
#pragma unroll
        for (int kk = 0; kk < 16; kk++) {
            ulonglong2 a01 = *(const ulonglong2*)&As2[kk][ty*4];
            ulonglong2 a23 = *(const ulonglong2*)&As2[kk][ty*4+2];
            ull a[4] = {a01.x, a01.y, a23.x, a23.y};
            ull bq[TN/2];
            if constexpr (TN == 8) {
                ulonglong2 b0 = *(const ulonglong2*)&Bsf[kk][tx*8];
                ulonglong2 b1 = *(const ulonglong2*)&Bsf[kk][tx*8+4];
                bq[0]=b0.x; bq[1]=b0.y; bq[2]=b1.x; bq[3]=b1.y;
            } else {
                ulonglong2 b0 = *(const ulonglong2*)&Bsf[kk][tx*4];
                bq[0]=b0.x; bq[1]=b0.y;
            }
#pragma unroll
            for (int m = 0; m < 4; m++)
#pragma unroll
                for (int j = 0; j < TN/2; j++)
                    acc[m][j] = fma2(a[m], bq[j], acc[m][j]);
        }
        __syncthreads();
        if (more) {
            if (aon) {
                As2[akq+0][am] = dup2(ra.x); As2[akq+1][am] = dup2(ra.y);
                As2[akq+2][am] = dup2(ra.z); As2[akq+3][am] = dup2(ra.w);
            }
#pragma unroll
            for (int j = 0; j < PER; j++) {
                Bsf[(bkq+j)*4+0][bn] = rb[j].x;
                Bsf[(bkq+j)*4+1][bn] = rb[j].y;
                Bsf[(bkq+j)*4+2][bn] = rb[j].z;
                Bsf[(bkq+j)*4+3][bn] = rb[j].w;
            }
        }
        __syncthreads();
    }

    const int nb = n0 + tx * TN;
#pragma unroll
    for (int m = 0; m < 4; m++) {
        float* cp = C + (long long)(ty*4+m) * ldc + nb;
#pragma unroll
        for (int j = 0; j < TN/2; j++) {
            float2 f = u2f(acc[m][j]);
            if (nb + 2*j     < N) atomicAdd(cp + 2*j,     f.x);
            if (nb + 2*j + 1 < N) atomicAdd(cp + 2*j + 1, f.y);
        }
    }
}

// ---------------- launch ----------------
extern "C" void kernel_launch(void* const* d_in, const int* in_sizes, int n_in,
                              void* d_out, int out_size)
{
    const float* x        = (const float*)d_in[0];
    const float* fc       = (const float*)d_in[1];
    const float* fs       = (const float*)d_in[2];
    const float* kvc      = (const float*)d_in[3];
    const float* pec      = (const float*)d_in[4];
    const float* wq_a     = (const float*)d_in[5];
    const float* q_norm_w = (const float*)d_in[6];
    const float* wq_b     = (const float*)d_in[7];
    const float* wkv_a    = (const float*)d_in[8];
    const float* kv_norm  = (const float*)d_in[9];
    const float* wkv_b    = (const float*)d_in[10];
    const float* wo       = (const float*)d_in[11];
    const int*   spos     = (const int*)d_in[12];
    float*       out      = (float*)d_out;

    float *qlat, *kvfull, *kvnew, *penew, *q, *qcat, *scores, *ml, *wv, *olat, *ohead;
    cudaGetSymbolAddress((void**)&qlat,   g_qlat);
    cudaGetSymbolAddress((void**)&kvfull, g_kvfull);
    cudaGetSymbolAddress((void**)&kvnew,  g_kvnew);
    cudaGetSymbolAddress((void**)&penew,  g_penew);
    cudaGetSymbolAddress((void**)&q,      g_q);
    cudaGetSymbolAddress((void**)&qcat,   g_qcat);
    cudaGetSymbolAddress((void**)&scores, g_scores);
    cudaGetSymbolAddress((void**)&ml,     g_ml);
    cudaGetSymbolAddress((void**)&wv,     g_w);
    cudaGetSymbolAddress((void**)&olat,   g_olat);
    cudaGetSymbolAddress((void**)&ohead,  g_ohead);

    cudaMemsetAsync(qlat,   0, (size_t)BATCH * QLR  * 4);
    cudaMemsetAsync(kvfull, 0, (size_t)BATCH * KCAT * 4);
    cudaMemsetAsync(q,      0, (size_t)BATCH * QDIM * 4);
    cudaMemsetAsync(olat,   0, (size_t)BATCH * H * KVLR * 4);
    cudaMemsetAsync(ohead,  0, (size_t)BATCH * ODIM * 4);
    cudaMemsetAsync(out,    0, (size_t)out_size * 4);

    dim3 blk(256);

    // q_lat = x @ wq_a^T   (N=1536, K=7168): 6 x 32 = 192 blocks
    gemv_mma<<<dim3(6,32,1), blk>>>(x, wq_a, qlat, DIM, DIM, QLR, 224);
    // kv_full = x @ wkv_a^T (N=576, K=7168): 3 x 64 = 192 blocks
    gemv_splitk<256,8><<<dim3(3,64,1), blk>>>(x, wkv_a, kvfull, KCAT, DIM, DIM, KCAT, 112, 0,0,0);
    rmsnorm_kernel<<<32, 256>>>(qlat, q_norm_w, QLR);
    kvprep_kernel<<<32, 256>>>(kvfull, kv_norm, fc, fs, kvnew, penew);
    // q = q_lat @ wq_b^T   (N=24576, K=1536): 96 x 6 = 576 blocks
    gemv_mma<<<dim3(96,6,1), blk>>>(qlat, wq_b, q, QLR, QLR, QDIM, 256);
    qrope_kernel<<<512, 256>>>(q, fc, fs, qcat);
    qabs_kernel<<<128, 512>>>(q, wkv_b, qcat);
    // scores + block-local softmax
    scores_sm<<<dim3(MAXS/256, H/64, BATCH), blk>>>(
        qcat, kvc, pec, kvnew, penew, scores, (float2*)ml, spos);
    // block weights
    wcomb_kernel<<<(BATCH*H + 255)/256, 256>>>((const float2*)ml, wv);
    // weighted olat: (2 c, 2hb x 4ks = 8, 32) = 512 blocks
    olat_w<<<dim3(KVLR/256, 8, BATCH), blk>>>(scores, kvc, kvnew, wv, olat, spos);
    // ohead per head
    gemv_splitk<128,4><<<dim3(1,1,H), blk>>>(olat, wkv_b + 128*KVLR, ohead,
                                             DV, H*KVLR, KVLR, ODIM, KVLR,
                                             (long long)KVLR, (long long)256*KVLR, (long long)DV);
    // out = ohead @ wo^T   (N=7168, K=16384): 28 x 16 = 448 blocks
    gemv_mma<<<dim3(28,16,1), blk>>>(ohead, wo, out, ODIM, ODIM, DIM, 1024);
}

// round 9
// speedup vs baseline: 1.6734x; 1.0071x over previous
#include <cuda_runtime.h>
#include <cuda_bf16.h>

// ---------------- problem constants ----------------
#define BATCH 32
#define DIM   7168
#define H     128
#define QLR   1536
#define KVLR  512
#define DN    128
#define DR    64
#define DV    128
#define QKD   192
#define MAXS  4096
#define QDIM  (H*QKD)      // 24576
#define KCAT  (KVLR+DR)    // 576
#define ODIM  (H*DV)       // 16384
#define NBLK  (MAXS/256)   // 16 t-blocks

#define SCALE_F 0.07216878364870322f
#define EPS_F   1e-6f

typedef unsigned long long ull;

// ---------------- helpers ----------------
__device__ __forceinline__ ull fma2(ull a, ull b, ull c) {
    ull d;
    asm("fma.rn.f32x2 %0, %1, %2, %3;" : "=l"(d) : "l"(a), "l"(b), "l"(c));
    return d;
}
__device__ __forceinline__ ull dup2(float x) {
    ull d;
    asm("mov.b64 %0, {%1, %1};" : "=l"(d) : "f"(x));
    return d;
}
__device__ __forceinline__ float2 u2f(ull v) {
    float2 f;
    f.x = __uint_as_float((unsigned)(v & 0xffffffffull));
    f.y = __uint_as_float((unsigned)(v >> 32));
    return f;
}
__device__ __forceinline__ unsigned f2tf(float f) {
    unsigned u; asm("cvt.rna.tf32.f32 %0, %1;" : "=r"(u) : "f"(f)); return u;
}
__device__ __forceinline__ void mma8(float* c, const unsigned* a, const unsigned* b) {
    asm volatile("mma.sync.aligned.m16n8k8.row.col.f32.tf32.tf32.f32 "
                 "{%0,%1,%2,%3}, {%4,%5,%6,%7}, {%8,%9}, {%0,%1,%2,%3};"
                 : "+f"(c[0]), "+f"(c[1]), "+f"(c[2]), "+f"(c[3])
                 : "r"(a[0]), "r"(a[1]), "r"(a[2]), "r"(a[3]),
                   "r"(b[0]), "r"(b[1]));
}

// ---------------- scratch ----------------
__device__ __align__(16) float g_qlat  [BATCH * QLR];
__device__ __align__(16) float g_kvfull[BATCH * KCAT];
__device__ __align__(16) float g_kvnew [BATCH * KVLR];
__device__ __align__(16) float g_penew [BATCH * DR];
__device__ __align__(16) float g_q     [BATCH * QDIM];
__device__ __align__(16) float g_qcat  [BATCH * H * KCAT];
__device__ __align__(16) float g_scores[(long long)BATCH * H * MAXS];
__device__ __align__(16) float g_ml    [BATCH * H * NBLK * 2];
__device__ __align__(16) float g_w     [BATCH * H * NBLK];
__device__ __align__(16) float g_olat  [BATCH * H * KVLR];
__device__ __align__(16) float g_ohead [BATCH * ODIM];

// ---------------- reductions ----------------
__device__ __forceinline__ float warpSum(float v) {
#pragma unroll
    for (int o = 16; o; o >>= 1) v += __shfl_xor_sync(0xffffffffu, v, o);
    return v;
}
__device__ __forceinline__ float blockSum256(float v) {
    __shared__ float sm[8];
    int lane = threadIdx.x & 31, w = threadIdx.x >> 5;
    __syncthreads();
    v = warpSum(v);
    if (!lane) sm[w] = v;
    __syncthreads();
    float r = 0.f;
#pragma unroll
    for (int i = 0; i < 8; i++) r += sm[i];
    return r;
}

// =====================================================================
// TF32 MMA split-K GEMV, double-buffered smem (1 sync / 16-k iter)
// =====================================================================
__global__ void __launch_bounds__(256) gemv_mma(
    const float* __restrict__ A, const float* __restrict__ B, float* __restrict__ C,
    int lda, int ldb, int ldc, int kChunk)
{
    const int n0 = blockIdx.x * 256;
    const int ks = blockIdx.y * kChunk;
    const int nIter = kChunk / 16;

    __shared__ unsigned As[2][16][40];
    __shared__ unsigned Bs[2][16][264];

    const int tid = threadIdx.x, lane = tid & 31, wid = tid >> 5;
    const int gid = lane >> 2, tig = lane & 3;
    const int wn = wid * 32;

    const bool aon = tid < 128;
    const int am = tid >> 2, akq = (tid & 3) * 4;
    const int acol = am ^ (8 * ((akq >> 2) & 3));
    const long long brow = (long long)(n0 + tid) * ldb;

    float4 ra = make_float4(0,0,0,0);
    float4 rb[4];

    if (aon) ra = *(const float4*)(A + (long long)am * lda + ks + akq);
#pragma unroll
    for (int j = 0; j < 4; j++) rb[j] = *(const float4*)(B + brow + ks + j*4);
    if (aon) {
        As[0][akq+0][acol] = f2tf(ra.x); As[0][akq+1][acol] = f2tf(ra.y);
        As[0][akq+2][acol] = f2tf(ra.z); As[0][akq+3][acol] = f2tf(ra.w);
    }
#pragma unroll
    for (int j = 0; j < 4; j++) {
        Bs[0][j*4+0][tid] = f2tf(rb[j].x); Bs[0][j*4+1][tid] = f2tf(rb[j].y);
        Bs[0][j*4+2][tid] = f2tf(rb[j].z); Bs[0][j*4+3][tid] = f2tf(rb[j].w);
    }
    __syncthreads();

    float acc[2][4][4];
#pragma unroll
    for (int mi = 0; mi < 2; mi++)
#pragma unroll
        for (int nj = 0; nj < 4; nj++)
#pragma unroll
            for (int r = 0; r < 4; r++) acc[mi][nj][r] = 0.f;

    for (int it = 0; it < nIter; it++) {
        const int cur = it & 1, nxt = cur ^ 1;
        const bool more = (it + 1) < nIter;
        const int k1 = ks + (it + 1) * 16;
        if (more) {
            if (aon) ra = *(const float4*)(A + (long long)am * lda + k1 + akq);
#pragma unroll
            for (int j = 0; j < 4; j++) rb[j] = *(const float4*)(B + brow + k1 + j*4);
        }
#pragma unroll
        for (int s = 0; s < 2; s++) {
            const int kk = s * 8;
            const int key0 = 8 * ((kk >> 2) & 3);
            const int key1 = 8 * (((kk >> 2) + 1) & 3);
            unsigned af[2][4];
#pragma unroll
            for (int mi = 0; mi < 2; mi++) {
                int r0 = mi*16 + gid;
                af[mi][0] = As[cur][kk+tig  ][ r0    ^ key0];
                af[mi][1] = As[cur][kk+tig  ][(r0+8) ^ key0];
                af[mi][2] = As[cur][kk+tig+4][ r0    ^ key1];
                af[mi][3] = As[cur][kk+tig+4][(r0+8) ^ key1];
            }
            unsigned bf[4][2];
#pragma unroll
            for (int nj = 0; nj < 4; nj++) {
                bf[nj][0] = Bs[cur][kk+tig  ][wn + nj*8 + gid];
                bf[nj][1] = Bs[cur][kk+tig+4][wn + nj*8 + gid];
            }
#pragma unroll
            for (int mi = 0; mi < 2; mi++)
#pragma unroll
                for (int nj = 0; nj < 4; nj++)
                    mma8(acc[mi][nj], af[mi], bf[nj]);
        }
        if (more) {
            if (aon) {
                As[nxt][akq+0][acol] = f2tf(ra.x); As[nxt][akq+1][acol] = f2tf(ra.y);
                As[nxt][akq+2][acol] = f2tf(ra.z); As[nxt][akq+3][acol] = f2tf(ra.w);
            }
#pragma unroll
            for (int j = 0; j < 4; j++) {
                Bs[nxt][j*4+0][tid] = f2tf(rb[j].x); Bs[nxt][j*4+1][tid] = f2tf(rb[j].y);
                Bs[nxt][j*4+2][tid] = f2tf(rb[j].z); Bs[nxt][j*4+3][tid] = f2tf(rb[j].w);
            }
        }
        __syncthreads();
    }

#pragma unroll
    for (int mi = 0; mi < 2; mi++)
#pragma unroll
        for (int nj = 0; nj < 4; nj++) {
            float* cp = C + (long long)(mi*16+gid)*ldc + n0 + wn + nj*8 + 2*tig;
            atomicAdd(cp,           acc[mi][nj][0]);
            atomicAdd(cp + 1,       acc[mi][nj][1]);
            atomicAdd(cp + 8*ldc,   acc[mi][nj][2]);
            atomicAdd(cp + 8*ldc+1, acc[mi][nj][3]);
        }
}

// ---------------- merged norms: blocks 0..31 rmsnorm(qlat), 32..63 kvprep ----------------
__global__ void __launch_bounds__(256) norms_kernel(
    float* __restrict__ qlat, const float* __restrict__ q_norm_w,
    const float* __restrict__ kvfull, const float* __restrict__ kv_norm,
    const float* __restrict__ fc, const float* __restrict__ fs,
    float* __restrict__ kvnew, float* __restrict__ penew)
{
    if (blockIdx.x < 32) {
        int b = blockIdx.x;
        float* row = qlat + (long long)b * QLR;
        float ss = 0.f;
        for (int i = threadIdx.x; i < QLR; i += 256) { float x = row[i]; ss += x * x; }
        ss = blockSum256(ss);
        __shared__ float s_scale;
        if (threadIdx.x == 0) s_scale = rsqrtf(ss / (float)QLR + EPS_F);
        __syncthreads();
        float sc = s_scale;
        for (int i = threadIdx.x; i < QLR; i += 256) row[i] = row[i] * sc * q_norm_w[i];
    } else {
        int b = blockIdx.x - 32;
        const float* row = kvfull + (long long)b * KCAT;
        float ss = 0.f;
        for (int i = threadIdx.x; i < KVLR; i += 256) { float x = row[i]; ss += x * x; }
        ss = blockSum256(ss);
        __shared__ float s_scale;
        if (threadIdx.x == 0) s_scale = rsqrtf(ss / (float)KVLR + EPS_F);
        __syncthreads();
        float sc = s_scale;
        for (int i = threadIdx.x; i < KVLR; i += 256)
            kvnew[(long long)b * KVLR + i] = row[i] * sc * kv_norm[i];
        if (threadIdx.x < 32) {
            int i = threadIdx.x;
            float x1 = row[KVLR + 2 * i], x2 = row[KVLR + 2 * i + 1];
            float c = fc[i], s = fs[i];
            penew[(long long)b * DR + 2 * i]     = x1 * c - x2 * s;
            penew[(long long)b * DR + 2 * i + 1] = x1 * s + x2 * c;
        }
    }
}

// ---------------- q rope -> qcat tail (scaled) ----------------
__global__ void __launch_bounds__(256) qrope_kernel(
    const float* __restrict__ q, const float* __restrict__ fc,
    const float* __restrict__ fs, float* __restrict__ qcat)
{
    int idx = blockIdx.x * 256 + threadIdx.x;
    if (idx >= BATCH * H * (DR / 2)) return;
    int i  = idx & 31;
    int bh = idx >> 5;
    int b  = bh >> 7, h = bh & 127;
    const float* src = q + (long long)b * QDIM + h * QKD + DN;
    float x1 = src[2 * i], x2 = src[2 * i + 1];
    float c = fc[i], s = fs[i];
    qcat[(long long)bh * KCAT + KVLR + 2 * i]     = (x1 * c - x2 * s) * SCALE_F;
    qcat[(long long)bh * KCAT + KVLR + 2 * i + 1] = (x1 * s + x2 * c) * SCALE_F;
}

// ---------------- q_abs (FFMA), 256 blocks: (h, column half) ----------------
__global__ void __launch_bounds__(256) qabs_kernel(
    const float* __restrict__ q, const float* __restrict__ wkvb, float* __restrict__ qcat)
{
    int h = blockIdx.x >> 1;
    int c = (blockIdx.x & 1) * 256 + threadIdx.x;
    __shared__ __align__(16) float sq[DN][BATCH];
    int tid = threadIdx.x;
#pragma unroll
    for (int i = 0; i < 16; i++) {
        int idx = tid + i * 256;
        int d = idx >> 5, b = idx & 31;
        sq[d][b] = q[(long long)b * QDIM + h * QKD + d];
    }
    __syncthreads();
    ull acc[16];
#pragma unroll
    for (int i = 0; i < 16; i++) acc[i] = 0ull;
    const float* w = wkvb + (long long)h * 256 * KVLR + c;
#pragma unroll 4
    for (int d = 0; d < DN; d++) {
        ull w2 = dup2(w[(long long)d * KVLR]);
#pragma unroll
        for (int bp = 0; bp < 16; bp++) {
            ull qp = *(const ull*)&sq[d][bp * 2];
            acc[bp] = fma2(qp, w2, acc[bp]);
        }
    }
#pragma unroll
    for (int bp = 0; bp < 16; bp++) {
        float2 f = u2f(acc[bp]);
        qcat[((long long)(2 * bp + 0) * H + h) * KCAT + c] = f.x * SCALE_F;
        qcat[((long long)(2 * bp + 1) * H + h) * KCAT + c] = f.y * SCALE_F;
    }
}

// ---------------- KV row loader ----------------
__device__ __forceinline__ void load_kvrow16(float4* rb,
        const float* __restrict__ kvc, const float* __restrict__ pec,
        const float* __restrict__ kvnew, const float* __restrict__ penew,
        int b, int t, int spos, int k0)
{
    const float* src;
    if (k0 < KVLR)
        src = (t == spos) ? (kvnew + (long long)b * KVLR + k0)
                          : (kvc + ((long long)b * MAXS + t) * KVLR + k0);
    else
        src = (t == spos) ? (penew + (long long)b * DR + (k0 - KVLR))
                          : (pec + ((long long)b * MAXS + t) * DR + (k0 - KVLR));
#pragma unroll
    for (int j = 0; j < 4; j++) rb[j] = *(const float4*)(src + j * 4);
}

// =====================================================================
// scores + block-local softmax, double-buffered
// =====================================================================
__global__ void __launch_bounds__(256) scores_sm(
    const float* __restrict__ qcat, const float* __restrict__ kvc, const float* __restrict__ pec,
    const float* __restrict__ kvnew, const float* __restrict__ penew,
    float* __restrict__ S, float2* __restrict__ mlv, const int* __restrict__ spos_p)
{
    const int b = blockIdx.z, spos = *spos_p;
    const int t0 = blockIdx.x * 256, h0 = blockIdx.y * 64;
    const float* A = qcat + ((long long)b * H + h0) * KCAT;
    float* C = S + ((long long)b * H + h0) * MAXS;

    __shared__ unsigned As[2][16][72];
    __shared__ unsigned Bs[2][16][264];
    __shared__ float red[64][4];

    const int tid = threadIdx.x, lane = tid & 31, wid = tid >> 5;
    const int gid = lane >> 2, tig = lane & 3;
    const int wh = (wid & 1) * 32, wt = (wid >> 1) * 64;
    const int wtq = wid >> 1;

    const int ah = tid >> 2, akq = (tid & 3) * 4;
    const int acol = ah ^ (8 * ((akq >> 2) & 3));
    const int bt = t0 + tid;

    float4 ra; float4 rb[4];
    ra = *(const float4*)(A + (long long)ah * KCAT + akq);
    load_kvrow16(rb, kvc, pec, kvnew, penew, b, bt, spos, 0);
    As[0][akq+0][acol] = f2tf(ra.x); As[0][akq+1][acol] = f2tf(ra.y);
    As[0][akq+2][acol] = f2tf(ra.z); As[0][akq+3][acol] = f2tf(ra.w);
#pragma unroll
    for (int j = 0; j < 4; j++) {
        Bs[0][j*4+0][tid] = f2tf(rb[j].x); Bs[0][j*4+1][tid] = f2tf(rb[j].y);
        Bs[0][j*4+2][tid] = f2tf(rb[j].z); Bs[0][j*4+3][tid] = f2tf(rb[j].w);
    }
    __syncthreads();

    float acc[2][8][4];
#pragma unroll
    for (int mi = 0; mi < 2; mi++)
#pragma unroll
        for (int nj = 0; nj < 8; nj++)
#pragma unroll
            for (int r = 0; r < 4; r++) acc[mi][nj][r] = 0.f;

    for (int it = 0; it < KCAT / 16; it++) {
        const int cur = it & 1, nxt = cur ^ 1;
        const bool more = (it + 1) < KCAT / 16;
        const int k1 = (it + 1) * 16;
        if (more) {
            ra = *(const float4*)(A + (long long)ah * KCAT + k1 + akq);
            load_kvrow16(rb, kvc, pec, kvnew, penew, b, bt, spos, k1);
        }
#pragma unroll
        for (int s = 0; s < 2; s++) {
            const int kk = s * 8;
            const int key0 = 8 * ((kk >> 2) & 3);
            const int key1 = 8 * (((kk >> 2) + 1) & 3);
            unsigned af[2][4];
#pragma unroll
            for (int mi = 0; mi < 2; mi++) {
                int r0 = wh + mi*16 + gid;
                af[mi][0] = As[cur][kk+tig  ][ r0    ^ key0];
                af[mi][1] = As[cur][kk+tig  ][(r0+8) ^ key0];
                af[mi][2] = As[cur][kk+tig+4][ r0    ^ key1];
                af[mi][3] = As[cur][kk+tig+4][(r0+8) ^ key1];
            }
            unsigned bf[8][2];
#pragma unroll
            for (int nj = 0; nj < 8; nj++) {
                bf[nj][0] = Bs[cur][kk+tig  ][wt + nj*8 + gid];
                bf[nj][1] = Bs[cur][kk+tig+4][wt + nj*8 + gid];
            }
#pragma unroll
            for (int mi = 0; mi < 2; mi++)
#pragma unroll
                for (int nj = 0; nj < 8; nj++)
                    mma8(acc[mi][nj], af[mi], bf[nj]);
        }
        if (more) {
            As[nxt][akq+0][acol] = f2tf(ra.x); As[nxt][akq+1][acol] = f2tf(ra.y);
            As[nxt][akq+2][acol] = f2tf(ra.z); As[nxt][akq+3][acol] = f2tf(ra.w);
#pragma unroll
            for (int j = 0; j < 4; j++) {
                Bs[nxt][j*4+0][tid] = f2tf(rb[j].x); Bs[nxt][j*4+1][tid] = f2tf(rb[j].y);
                Bs[nxt][j*4+2][tid] = f2tf(rb[j].z); Bs[nxt][j*4+3][tid] = f2tf(rb[j].w);
            }
        }
        __syncthreads();
    }

    // ---------------- block-local softmax epilogue ----------------
    float m_lo[2], m_hi[2];
#pragma unroll
    for (int mi = 0; mi < 2; mi++) {
        float a = -1e30f, c = -1e30f;
#pragma unroll
        for (int nj = 0; nj < 8; nj++) {
            int t = t0 + wt + nj*8 + 2*tig;
            float v0 = (t     <= spos) ? acc[mi][nj][0] : -1e30f;
            float v1 = (t + 1 <= spos) ? acc[mi][nj][1] : -1e30f;
            float v2 = (t     <= spos) ? acc[mi][nj][2] : -1e30f;
            float v3 = (t + 1 <= spos) ? acc[mi][nj][3] : -1e30f;
            a = fmaxf(a, fmaxf(v0, v1));
            c = fmaxf(c, fmaxf(v2, v3));
        }
        a = fmaxf(a, __shfl_xor_sync(0xffffffffu, a, 1));
        a = fmaxf(a, __shfl_xor_sync(0xffffffffu, a, 2));
        c = fmaxf(c, __shfl_xor_sync(0xffffffffu, c, 1));
        c = fmaxf(c, __shfl_xor_sync(0xffffffffu, c, 2));
        m_lo[mi] = a; m_hi[mi] = c;
    }
    if (tig == 0) {
#pragma unroll
        for (int mi = 0; mi < 2; mi++) {
            red[wh + mi*16 + gid    ][wtq] = m_lo[mi];
            red[wh + mi*16 + gid + 8][wtq] = m_hi[mi];
        }
    }
    __syncthreads();
#pragma unroll
    for (int mi = 0; mi < 2; mi++) {
        int r = wh + mi*16 + gid;
        m_lo[mi] = fmaxf(fmaxf(red[r][0],   red[r][1]),   fmaxf(red[r][2],   red[r][3]));
        m_hi[mi] = fmaxf(fmaxf(red[r+8][0], red[r+8][1]), fmaxf(red[r+8][2], red[r+8][3]));
    }
    __syncthreads();
    float s_lo[2] = {0.f, 0.f}, s_hi[2] = {0.f, 0.f};
#pragma unroll
    for (int mi = 0; mi < 2; mi++) {
#pragma unroll
        for (int nj = 0; nj < 8; nj++) {
            int t = t0 + wt + nj*8 + 2*tig;
            float e0 = (t     <= spos) ? __expf(acc[mi][nj][0] - m_lo[mi]) : 0.f;
            float e1 = (t + 1 <= spos) ? __expf(acc[mi][nj][1] - m_lo[mi]) : 0.f;
            float e2 = (t     <= spos) ? __expf(acc[mi][nj][2] - m_hi[mi]) : 0.f;
            float e3 = (t + 1 <= spos) ? __expf(acc[mi][nj][3] - m_hi[mi]) : 0.f;
            acc[mi][nj][0] = e0; acc[mi][nj][1] = e1;
            acc[mi][nj][2] = e2; acc[mi][nj][3] = e3;
            s_lo[mi] += e0 + e1; s_hi[mi] += e2 + e3;
        }
        s_lo[mi] += __shfl_xor_sync(0xffffffffu, s_lo[mi], 1);
        s_lo[mi] += __shfl_xor_sync(0xffffffffu, s_lo[mi], 2);
        s_hi[mi] += __shfl_xor_sync(0xffffffffu, s_hi[mi], 1);
        s_hi[mi] += __shfl_xor_sync(0xffffffffu, s_hi[mi], 2);
    }
    if (tig == 0) {
#pragma unroll
        for (int mi = 0; mi < 2; mi++) {
            red[wh + mi*16 + gid    ][wtq] = s_lo[mi];
            red[wh + mi*16 + gid + 8][wtq] = s_hi[mi];
        }
    }
    __syncthreads();
    if (wtq == 0 && tig == 0) {
#pragma unroll
        for (int mi = 0; mi < 2; mi++) {
            int r = wh + mi*16 + gid;
            float l0 = red[r][0]   + red[r][1]   + red[r][2]   + red[r][3];
            float l1 = red[r+8][0] + red[r+8][1] + red[r+8][2] + red[r+8][3];
            mlv[((long long)(b * H + h0 + r))     * NBLK + blockIdx.x] = make_float2(m_lo[mi], l0);
            mlv[((long long)(b * H + h0 + r + 8)) * NBLK + blockIdx.x] = make_float2(m_hi[mi], l1);
        }
    }

    // write P'
#pragma unroll
    for (int mi = 0; mi < 2; mi++)
#pragma unroll
        for (int nj = 0; nj < 8; nj++) {
            float* cp = C + (long long)(wh + mi*16 + gid) * MAXS + t0 + wt + nj*8 + 2*tig;
            *(float2*)cp            = make_float2(acc[mi][nj][0], acc[mi][nj][1]);
            *(float2*)(cp + 8*MAXS) = make_float2(acc[mi][nj][2], acc[mi][nj][3]);
        }
}

// ---------------- combine weights ----------------
__global__ void __launch_bounds__(256) wcomb_kernel(
    const float2* __restrict__ mlv, float* __restrict__ wv)
{
    int row = blockIdx.x * 256 + threadIdx.x;
    if (row >= BATCH * H) return;
    const float2* p = mlv + (long long)row * NBLK;
    float2 v[NBLK];
    float M = -1e30f;
#pragma unroll
    for (int i = 0; i < NBLK; i++) { v[i] = p[i]; M = fmaxf(M, v[i].x); }
    float L = 0.f;
#pragma unroll
    for (int i = 0; i < NBLK; i++) L += __expf(v[i].x - M) * v[i].y;
    float inv = 1.f / L;
#pragma unroll
    for (int i = 0; i < NBLK; i++)
        wv[(long long)row * NBLK + i] = __expf(v[i].x - M) * inv;
}

// =====================================================================
// olat: tile 64h x 256c, split-k over t (8), atomicAdd, double-buffered
// =====================================================================
__global__ void __launch_bounds__(256) olat_w(
    const float* __restrict__ P, const float* __restrict__ kvc,
    const float* __restrict__ kvnew, const float* __restrict__ wv,
    float* __restrict__ O, const int* __restrict__ spos_p)
{
    const int b = blockIdx.z, spos = *spos_p;
    const int c0 = blockIdx.x * 256;
    const int hb = blockIdx.y >> 3, ks = blockIdx.y & 7;
    const int h0 = hb * 64;
    const float* A = P + ((long long)b * H + h0) * MAXS;
    float* C = O + ((long long)b * H + h0) * KVLR;

    __shared__ unsigned As[2][16][72];
    __shared__ unsigned Bs[2][16][264];
    __shared__ float ws[64][16];

    const int tid = threadIdx.x, lane = tid & 31, wid = tid >> 5;
    const int gid = lane >> 2, tig = lane & 3;
    const int wh = (wid & 1) * 32, wc = (wid >> 1) * 64;

#pragma unroll
    for (int j = 0; j < 4; j++) {
        int idx = tid * 4 + j;
        int r = idx >> 4, blk = idx & 15;
        ws[r][blk] = wv[((long long)(b * H + h0 + r)) * NBLK + blk];
    }
    __syncthreads();

    const int ah = tid >> 2, akq = (tid & 3) * 4;
    const int acol = ah ^ (8 * ((akq >> 2) & 3));
    const int kbeg = ks * (MAXS/8);
    const int nIter = (MAXS/8) / 16;

    float4 ra; float4 rb[4];
    {
        float w0 = ws[ah][kbeg >> 8];
        ra = *(const float4*)(A + (long long)ah * MAXS + kbeg + akq);
        ra.x *= w0; ra.y *= w0; ra.z *= w0; ra.w *= w0;
    }
#pragma unroll
    for (int j = 0; j < 4; j++) {
        int idx = tid + j * 256;
        int r = idx >> 6, c4 = (idx & 63) * 4;
        int t = kbeg + r;
        const float* src = (t == spos) ? (kvnew + (long long)b * KVLR + c0 + c4)
                                       : (kvc + ((long long)b * MAXS + t) * KVLR + c0 + c4);
        rb[j] = *(const float4*)src;
    }
    As[0][akq+0][acol] = f2tf(ra.x); As[0][akq+1][acol] = f2tf(ra.y);
    As[0][akq+2][acol] = f2tf(ra.z); As[0][akq+3][acol] = f2tf(ra.w);
#pragma unroll
    for (int j = 0; j < 4; j++) {
        int idx = tid + j * 256;
        int r = idx >> 6, c4 = (idx & 63) * 4;
        uint4 u = make_uint4(f2tf(rb[j].x), f2tf(rb[j].y), f2tf(rb[j].z), f2tf(rb[j].w));
        *(uint4*)&Bs[0][r][c4] = u;
    }
    __syncthreads();

    float acc[2][8][4];
#pragma unroll
    for (int mi = 0; mi < 2; mi++)
#pragma unroll
        for (int nj = 0; nj < 8; nj++)
#pragma unroll
            for (int r = 0; r < 4; r++) acc[mi][nj][r] = 0.f;

    for (int it = 0; it < nIter; it++) {
        const int cur = it & 1, nxt = cur ^ 1;
        const bool more = (it + 1) < nIter;
        const int k1 = kbeg + (it + 1) * 16;
        if (more) {
            float w0 = ws[ah][k1 >> 8];
            ra = *(const float4*)(A + (long long)ah * MAXS + k1 + akq);
            ra.x *= w0; ra.y *= w0; ra.z *= w0; ra.w *= w0;
#pragma unroll
            for (int j = 0; j < 4; j++) {
                int idx = tid + j * 256;
                int r = idx >> 6, c4 = (idx & 63) * 4;
                int t = k1 + r;
                const float* src = (t == spos) ? (kvnew + (long long)b * KVLR + c0 + c4)
                                               : (kvc + ((long long)b * MAXS + t) * KVLR + c0 + c4);
                rb[j] = *(const float4*)src;
            }
        }
#pragma unroll
        for (int s = 0; s < 2; s++) {
            const int kk = s * 8;
            const int key0 = 8 * ((kk >> 2) & 3);
            const int key1 = 8 * (((kk >> 2) + 1) & 3);
            unsigned af[2][4];
#pragma unroll
            for (int mi = 0; mi < 2; mi++) {
                int r0 = wh + mi*16 + gid;
                af[mi][0] = As[cur][kk+tig  ][ r0    ^ key0];
                af[mi][1] = As[cur][kk+tig  ][(r0+8) ^ key0];
                af[mi][2] = As[cur][kk+tig+4][ r0    ^ key1];
                af[mi][3] = As[cur][kk+tig+4][(r0+8) ^ key1];
            }
            unsigned bf[8][2];
#pragma unroll
            for (int nj = 0; nj < 8; nj++) {
                bf[nj][0] = Bs[cur][kk+tig  ][wc + nj*8 + gid];
                bf[nj][1] = Bs[cur][kk+tig+4][wc + nj*8 + gid];
            }
#pragma unroll
            for (int mi = 0; mi < 2; mi++)
#pragma unroll
                for (int nj = 0; nj < 8; nj++)
                    mma8(acc[mi][nj], af[mi], bf[nj]);
        }
        if (more) {
            As[nxt][akq+0][acol] = f2tf(ra.x); As[nxt][akq+1][acol] = f2tf(ra.y);
            As[nxt][akq+2][acol] = f2tf(ra.z); As[nxt][akq+3][acol] = f2tf(ra.w);
#pragma unroll
            for (int j = 0; j < 4; j++) {
                int idx = tid + j * 256;
                int r = idx >> 6, c4 = (idx & 63) * 4;
                uint4 u = make_uint4(f2tf(rb[j].x), f2tf(rb[j].y), f2tf(rb[j].z), f2tf(rb[j].w));
                *(uint4*)&Bs[nxt][r][c4] = u;
            }
        }
        __syncthreads();
    }

#pragma unroll
    for (int mi = 0; mi < 2; mi++)
#pragma unroll
        for (int nj = 0; nj < 8; nj++) {
            float* cp = C + (long long)(wh + mi*16 + gid) * KVLR + c0 + wc + nj*8 + 2*tig;
            atomicAdd(cp,            acc[mi][nj][0]);
            atomicAdd(cp + 1,        acc[mi][nj][1]);
            atomicAdd(cp + 8*KVLR,   acc[mi][nj][2]);
            atomicAdd(cp + 8*KVLR+1, acc[mi][nj][3]);
        }
}

// =====================================================================
// FFMA split-K GEMV (kvfull, ohead)
// =====================================================================
template<int BN, int TN>
__global__ void __launch_bounds__(256) gemv_splitk(
    const float* __restrict__ A, const float* __restrict__ B, float* __restrict__ C,
    int N, int lda, int ldb, int ldc, int kChunk,
    long long aB, long long bB, long long cB)
{
    A += (long long)blockIdx.z * aB;
    B += (long long)blockIdx.z * bB;
    C += (long long)blockIdx.z * cB;
    const int n0 = blockIdx.x * BN;
    const int ks = blockIdx.y * kChunk;
    const int ke = ks + kChunk;

    __shared__ __align__(16) ull   As2[16][32];
    __shared__ __align__(16) float Bsf [16][BN];

    const int tid = threadIdx.x;
    const int tx = tid & 31, ty = tid >> 5;

    const bool aon = tid < 128;
    const int am = tid >> 2, akq = (tid & 3) << 2;
    constexpr int PER = BN / 64;
    const int bn  = tid % BN;
    const int bkq = (tid / BN) * PER;
    const bool bon = (n0 + bn) < N;

    float4 ra = make_float4(0,0,0,0);
    float4 rb[PER];
#pragma unroll
    for (int j = 0; j < PER; j++) rb[j] = make_float4(0,0,0,0);

    if (aon) ra = *(const float4*)(A + (long long)am * lda + ks + akq);
    if (bon) {
        const float* bp = B + (long long)(n0 + bn) * ldb + ks + bkq * 4;
#pragma unroll
        for (int j = 0; j < PER; j++) rb[j] = *(const float4*)(bp + j * 4);
    }
    if (aon) {
        As2[akq+0][am] = dup2(ra.x); As2[akq+1][am] = dup2(ra.y);
        As2[akq+2][am] = dup2(ra.z); As2[akq+3][am] = dup2(ra.w);
    }
#pragma unroll
    for (int j = 0; j < PER; j++) {
        Bsf[(bkq+j)*4+0][bn] = rb[j].x;
        Bsf[(bkq+j)*4+1][bn] = rb[j].y;
        Bsf[(bkq+j)*4+2][bn] = rb[j].z;
        Bsf[(bkq+j)*4+3][bn] = rb[j].w;
    }
    __syncthreads();

    ull acc[4][TN/2];
#pragma unroll
    for (int m = 0; m < 4; m++)
#pragma unroll
        for (int j = 0; j < TN/2; j++) acc[m][j] = 0ull;

    for (int k0 = ks; k0 < ke; k0 += 16) {
        const bool more = (k0 + 16) < ke;
        if (more) {
            if (aon) ra = *(const float4*)(A + (long long)am * lda + (k0+16) + akq);
            if (bon) {
                const float* bp = B + (long long)(n0 + bn) * ldb + (k0+16) + bkq * 4;
#pragma unroll
                for (int j = 0; j < PER; j++) rb[j] = *(const float4*)(bp + j * 4);
            }
        }
#pragma unroll
        for (int kk = 0; kk < 16; kk++) {
            ulonglong2 a01 = *(const ulonglong2*)&As2[kk][ty*4];
            ulonglong2 a23 = *(const ulonglong2*)&As2[kk][ty*4+2];
            ull a[4] = {a01.x, a01.y, a23.x, a23.y};
            ull bq[TN/2];
            if constexpr (TN == 8) {
                ulonglong2 b0 = *(const ulonglong2*)&Bsf[kk][tx*8];
                ulonglong2 b1 = *(const ulonglong2*)&Bsf[kk][tx*8+4];
                bq[0]=b0.x; bq[1]=b0.y; bq[2]=b1.x; bq[3]=b1.y;
            } else {
                ulonglong2 b0 = *(const ulonglong2*)&Bsf[kk][tx*4];
                bq[0]=b0.x; bq[1]=b0.y;
            }
#pragma unroll
            for (int m = 0; m < 4; m++)
#pragma unroll
                for (int j = 0; j < TN/2; j++)
                    acc[m][j] = fma2(a[m], bq[j], acc[m][j]);
        }
        __syncthreads();
        if (more) {
            if (aon) {
                As2[akq+0][am] = dup2(ra.x); As2[akq+1][am] = dup2(ra.y);
                As2[akq+2][am] = dup2(ra.z); As2[akq+3][am] = dup2(ra.w);
            }
#pragma unroll
            for (int j = 0; j < PER; j++) {
                Bsf[(bkq+j)*4+0][bn] = rb[j].x;
                Bsf[(bkq+j)*4+1][bn] = rb[j].y;
                Bsf[(bkq+j)*4+2][bn] = rb[j].z;
                Bsf[(bkq+j)*4+3][bn] = rb[j].w;
            }
        }
        __syncthreads();
    }

    const int nb = n0 + tx * TN;
#pragma unroll
    for (int m = 0; m < 4; m++) {
        float* cp = C + (long long)(ty*4+m) * ldc + nb;
#pragma unroll
        for (int j = 0; j < TN/2; j++) {
            float2 f = u2f(acc[m][j]);
            if (nb + 2*j     < N) atomicAdd(cp + 2*j,     f.x);
            if (nb + 2*j + 1 < N) atomicAdd(cp + 2*j + 1, f.y);
        }
    }
}

// ---------------- launch ----------------
extern "C" void kernel_launch(void* const* d_in, const int* in_sizes, int n_in,
                              void* d_out, int out_size)
{
    const float* x        = (const float*)d_in[0];
    const float* fc       = (const float*)d_in[1];
    const float* fs       = (const float*)d_in[2];
    const float* kvc      = (const float*)d_in[3];
    const float* pec      = (const float*)d_in[4];
    const float* wq_a     = (const float*)d_in[5];
    const float* q_norm_w = (const float*)d_in[6];
    const float* wq_b     = (const float*)d_in[7];
    const float* wkv_a    = (const float*)d_in[8];
    const float* kv_norm  = (const float*)d_in[9];
    const float* wkv_b    = (const float*)d_in[10];
    const float* wo       = (const float*)d_in[11];
    const int*   spos     = (const int*)d_in[12];
    float*       out      = (float*)d_out;

    float *qlat, *kvfull, *kvnew, *penew, *q, *qcat, *scores, *ml, *wv, *olat, *ohead;
    cudaGetSymbolAddress((void**)&qlat,   g_qlat);
    cudaGetSymbolAddress((void**)&kvfull, g_kvfull);
    cudaGetSymbolAddress((void**)&kvnew,  g_kvnew);
    cudaGetSymbolAddress((void**)&penew,  g_penew);
    cudaGetSymbolAddress((void**)&q,      g_q);
    cudaGetSymbolAddress((void**)&qcat,   g_qcat);
    cudaGetSymbolAddress((void**)&scores, g_scores);
    cudaGetSymbolAddress((void**)&ml,     g_ml);
    cudaGetSymbolAddress((void**)&wv,     g_w);
    cudaGetSymbolAddress((void**)&olat,   g_olat);
    cudaGetSymbolAddress((void**)&ohead,  g_ohead);

    cudaMemsetAsync(qlat,   0, (size_t)BATCH * QLR  * 4);
    cudaMemsetAsync(kvfull, 0, (size_t)BATCH * KCAT * 4);
    cudaMemsetAsync(q,      0, (size_t)BATCH * QDIM * 4);
    cudaMemsetAsync(olat,   0, (size_t)BATCH * H * KVLR * 4);
    cudaMemsetAsync(ohead,  0, (size_t)BATCH * ODIM * 4);
    cudaMemsetAsync(out,    0, (size_t)out_size * 4);

    dim3 blk(256);

    // q_lat = x @ wq_a^T   (N=1536, K=7168): 192 blocks
    gemv_mma<<<dim3(6,32,1), blk>>>(x, wq_a, qlat, DIM, DIM, QLR, 224);
    // kv_full = x @ wkv_a^T (N=576, K=7168): 192 blocks
    gemv_splitk<256,8><<<dim3(3,64,1), blk>>>(x, wkv_a, kvfull, KCAT, DIM, DIM, KCAT, 112, 0,0,0);
    // merged rmsnorm(qlat) + kvprep
    norms_kernel<<<64, 256>>>(qlat, q_norm_w, kvfull, kv_norm, fc, fs, kvnew, penew);
    // q = q_lat @ wq_b^T   (N=24576, K=1536): 96 x 12 = 1152 blocks
    gemv_mma<<<dim3(96,12,1), blk>>>(qlat, wq_b, q, QLR, QLR, QDIM, 128);
    qrope_kernel<<<512, 256>>>(q, fc, fs, qcat);
    // q_abs: 256 blocks (h x column-half)
    qabs_kernel<<<256, 256>>>(q, wkv_b, qcat);
    // scores + block-local softmax: 1024 blocks
    scores_sm<<<dim3(MAXS/256, H/64, BATCH), blk>>>(
        qcat, kvc, pec, kvnew, penew, scores, (float2*)ml, spos);
    // block weights
    wcomb_kernel<<<(BATCH*H + 255)/256, 256>>>((const float2*)ml, wv);
    // weighted olat: (2 c, 2hb x 8ks = 16, 32) = 1024 blocks
    olat_w<<<dim3(KVLR/256, 16, BATCH), blk>>>(scores, kvc, kvnew, wv, olat, spos);
    // ohead per head, 2 k-splits: 256 blocks
    gemv_splitk<128,4><<<dim3(1,2,H), blk>>>(olat, wkv_b + 128*KVLR, ohead,
                                             DV, H*KVLR, KVLR, ODIM, 256,
                                             (long long)KVLR, (long long)256*KVLR, (long long)DV);
    // out = ohead @ wo^T   (N=7168, K=16384): 28 x 32 = 896 blocks
    gemv_mma<<<dim3(28,32,1), blk>>>(ohead, wo, out, ODIM, ODIM, DIM, 512);
}

// round 10
// speedup vs baseline: 1.8296x; 1.0933x over previous
#include <cuda_runtime.h>
#include <cuda_bf16.h>

// ---------------- problem constants ----------------
#define BATCH 32
#define DIM   7168
#define H     128
#define QLR   1536
#define KVLR  512
#define DN    128
#define DR    64
#define DV    128
#define QKD   192
#define MAXS  4096
#define QDIM  (H*QKD)      // 24576
#define KCAT  (KVLR+DR)    // 576
#define ODIM  (H*DV)       // 16384
#define NBLK  (MAXS/256)   // 16 t-blocks

#define SCALE_F 0.07216878364870322f
#define EPS_F   1e-6f

typedef unsigned long long ull;

// ---------------- helpers ----------------
__device__ __forceinline__ ull fma2(ull a, ull b, ull c) {
    ull d;
    asm("fma.rn.f32x2 %0, %1, %2, %3;" : "=l"(d) : "l"(a), "l"(b), "l"(c));
    return d;
}
__device__ __forceinline__ ull dup2(float x) {
    ull d;
    asm("mov.b64 %0, {%1, %1};" : "=l"(d) : "f"(x));
    return d;
}
__device__ __forceinline__ float2 u2f(ull v) {
    float2 f;
    f.x = __uint_as_float((unsigned)(v & 0xffffffffull));
    f.y = __uint_as_float((unsigned)(v >> 32));
    return f;
}
__device__ __forceinline__ unsigned f2tf(float f) {
    unsigned u; asm("cvt.rna.tf32.f32 %0, %1;" : "=r"(u) : "f"(f)); return u;
}
__device__ __forceinline__ void mma8(float* c, const unsigned* a, const unsigned* b) {
    asm volatile("mma.sync.aligned.m16n8k8.row.col.f32.tf32.tf32.f32 "
                 "{%0,%1,%2,%3}, {%4,%5,%6,%7}, {%8,%9}, {%0,%1,%2,%3};"
                 : "+f"(c[0]), "+f"(c[1]), "+f"(c[2]), "+f"(c[3])
                 : "r"(a[0]), "r"(a[1]), "r"(a[2]), "r"(a[3]),
                   "r"(b[0]), "r"(b[1]));
}

// ---------------- scratch ----------------
__device__ __align__(16) float g_qlat  [BATCH * QLR];
__device__ __align__(16) float g_kvfull[BATCH * KCAT];
__device__ __align__(16) float g_kvnew [BATCH * KVLR];
__device__ __align__(16) float g_penew [BATCH * DR];
__device__ __align__(16) float g_q     [BATCH * QDIM];
__device__ __align__(16) float g_qcat  [BATCH * H * KCAT];
__device__ __align__(16) float g_scores[(long long)BATCH * H * MAXS];
__device__ __align__(16) float g_ml    [BATCH * H * NBLK * 2];
__device__ __align__(16) float g_w     [BATCH * H * NBLK];
__device__ __align__(16) float g_olat  [BATCH * H * KVLR];
__device__ __align__(16) float g_ohead [BATCH * ODIM];

// ---------------- reductions ----------------
__device__ __forceinline__ float warpSum(float v) {
#pragma unroll
    for (int o = 16; o; o >>= 1) v += __shfl_xor_sync(0xffffffffu, v, o);
    return v;
}
__device__ __forceinline__ float blockSum256(float v) {
    __shared__ float sm[8];
    int lane = threadIdx.x & 31, w = threadIdx.x >> 5;
    __syncthreads();
    v = warpSum(v);
    if (!lane) sm[w] = v;
    __syncthreads();
    float r = 0.f;
#pragma unroll
    for (int i = 0; i < 8; i++) r += sm[i];
    return r;
}

// =====================================================================
// TF32 MMA split-K GEMV, v2: B fragments DIRECT from global (LDG.64,
// k-permuted: mma-k tig <-> global 2tig, tig+4 <-> 2tig+1), A staged
// in XOR-swizzled smem (double-buffered). No B smem round-trip.
// =====================================================================
__global__ void __launch_bounds__(256) gemv_mma(
    const float* __restrict__ A, const float* __restrict__ B, float* __restrict__ C,
    int lda, int ldb, int ldc, int kChunk)
{
    const int n0 = blockIdx.x * 256;
    const int ks = blockIdx.y * kChunk;
    const int nIter = kChunk / 16;

    __shared__ unsigned As[2][16][40];

    const int tid = threadIdx.x, lane = tid & 31, wid = tid >> 5;
    const int gid = lane >> 2, tig = lane & 3;
    const int wn = wid * 32;

    const bool aon = tid < 128;
    const int am = tid >> 2, akq = (tid & 3) * 4;
    const int acol = am ^ (8 * ((akq >> 2) & 3));

    // B fragment row pointers (ks and 2*tig folded in)
    const float* brow[4];
#pragma unroll
    for (int nj = 0; nj < 4; nj++)
        brow[nj] = B + (long long)(n0 + wn + nj*8 + gid) * ldb + ks + 2*tig;

    // prologue: A tile 0 -> smem buf 0; B group 0 -> regs
    float4 ra = make_float4(0,0,0,0);
    if (aon) ra = *(const float4*)(A + (long long)am * lda + ks + akq);
    ull bcur[4];
#pragma unroll
    for (int nj = 0; nj < 4; nj++) bcur[nj] = *(const ull*)(brow[nj]);
    if (aon) {
        As[0][akq+0][acol] = f2tf(ra.x); As[0][akq+1][acol] = f2tf(ra.y);
        As[0][akq+2][acol] = f2tf(ra.z); As[0][akq+3][acol] = f2tf(ra.w);
    }
    __syncthreads();

    float acc[2][4][4];
#pragma unroll
    for (int mi = 0; mi < 2; mi++)
#pragma unroll
        for (int nj = 0; nj < 4; nj++)
#pragma unroll
            for (int r = 0; r < 4; r++) acc[mi][nj][r] = 0.f;

    for (int it = 0; it < nIter; it++) {
        const int cur = it & 1, nxt = cur ^ 1;
        const bool more = (it + 1) < nIter;
        if (more && aon)
            ra = *(const float4*)(A + (long long)am * lda + ks + (it+1)*16 + akq);
#pragma unroll
        for (int s = 0; s < 2; s++) {
            const int koff = it*16 + s*8;
            // prefetch next B k8-group
            ull bnxt[4];
            const bool hasnext = (koff + 8) < kChunk;
            if (hasnext) {
#pragma unroll
                for (int nj = 0; nj < 4; nj++)
                    bnxt[nj] = *(const ull*)(brow[nj] + koff + 8);
            }
            // A fragments: smem rows s*8+2tig, s*8+2tig+1
            const int rlo = s*8 + 2*tig;
            const int key = 8 * ((rlo >> 2) & 3);
            unsigned af[2][4];
#pragma unroll
            for (int mi = 0; mi < 2; mi++) {
                int r0 = mi*16 + gid;
                af[mi][0] = As[cur][rlo  ][ r0    ^ key];
                af[mi][1] = As[cur][rlo  ][(r0+8) ^ key];
                af[mi][2] = As[cur][rlo+1][ r0    ^ key];
                af[mi][3] = As[cur][rlo+1][(r0+8) ^ key];
            }
            // B fragments from registers (convert to tf32)
            unsigned bf[4][2];
#pragma unroll
            for (int nj = 0; nj < 4; nj++) {
                float2 f = u2f(bcur[nj]);
                bf[nj][0] = f2tf(f.x);
                bf[nj][1] = f2tf(f.y);
            }
#pragma unroll
            for (int mi = 0; mi < 2; mi++)
#pragma unroll
                for (int nj = 0; nj < 4; nj++)
                    mma8(acc[mi][nj], af[mi], bf[nj]);
            if (hasnext) {
#pragma unroll
                for (int nj = 0; nj < 4; nj++) bcur[nj] = bnxt[nj];
            }
        }
        if (more && aon) {
            As[nxt][akq+0][acol] = f2tf(ra.x); As[nxt][akq+1][acol] = f2tf(ra.y);
            As[nxt][akq+2][acol] = f2tf(ra.z); As[nxt][akq+3][acol] = f2tf(ra.w);
        }
        __syncthreads();
    }

#pragma unroll
    for (int mi = 0; mi < 2; mi++)
#pragma unroll
        for (int nj = 0; nj < 4; nj++) {
            float* cp = C + (long long)(mi*16+gid)*ldc + n0 + wn + nj*8 + 2*tig;
            atomicAdd(cp,           acc[mi][nj][0]);
            atomicAdd(cp + 1,       acc[mi][nj][1]);
            atomicAdd(cp + 8*ldc,   acc[mi][nj][2]);
            atomicAdd(cp + 8*ldc+1, acc[mi][nj][3]);
        }
}

// ---------------- merged norms: blocks 0..31 rmsnorm(qlat), 32..63 kvprep ----------------
__global__ void __launch_bounds__(256) norms_kernel(
    float* __restrict__ qlat, const float* __restrict__ q_norm_w,
    const float* __restrict__ kvfull, const float* __restrict__ kv_norm,
    const float* __restrict__ fc, const float* __restrict__ fs,
    float* __restrict__ kvnew, float* __restrict__ penew)
{
    if (blockIdx.x < 32) {
        int b = blockIdx.x;
        float* row = qlat + (long long)b * QLR;
        float ss = 0.f;
        for (int i = threadIdx.x; i < QLR; i += 256) { float x = row[i]; ss += x * x; }
        ss = blockSum256(ss);
        __shared__ float s_scale;
        if (threadIdx.x == 0) s_scale = rsqrtf(ss / (float)QLR + EPS_F);
        __syncthreads();
        float sc = s_scale;
        for (int i = threadIdx.x; i < QLR; i += 256) row[i] = row[i] * sc * q_norm_w[i];
    } else {
        int b = blockIdx.x - 32;
        const float* row = kvfull + (long long)b * KCAT;
        float ss = 0.f;
        for (int i = threadIdx.x; i < KVLR; i += 256) { float x = row[i]; ss += x * x; }
        ss = blockSum256(ss);
        __shared__ float s_scale;
        if (threadIdx.x == 0) s_scale = rsqrtf(ss / (float)KVLR + EPS_F);
        __syncthreads();
        float sc = s_scale;
        for (int i = threadIdx.x; i < KVLR; i += 256)
            kvnew[(long long)b * KVLR + i] = row[i] * sc * kv_norm[i];
        if (threadIdx.x < 32) {
            int i = threadIdx.x;
            float x1 = row[KVLR + 2 * i], x2 = row[KVLR + 2 * i + 1];
            float c = fc[i], s = fs[i];
            penew[(long long)b * DR + 2 * i]     = x1 * c - x2 * s;
            penew[(long long)b * DR + 2 * i + 1] = x1 * s + x2 * c;
        }
    }
}

// ---------------- q rope -> qcat tail (scaled) ----------------
__global__ void __launch_bounds__(256) qrope_kernel(
    const float* __restrict__ q, const float* __restrict__ fc,
    const float* __restrict__ fs, float* __restrict__ qcat)
{
    int idx = blockIdx.x * 256 + threadIdx.x;
    if (idx >= BATCH * H * (DR / 2)) return;
    int i  = idx & 31;
    int bh = idx >> 5;
    int b  = bh >> 7, h = bh & 127;
    const float* src = q + (long long)b * QDIM + h * QKD + DN;
    float x1 = src[2 * i], x2 = src[2 * i + 1];
    float c = fc[i], s = fs[i];
    qcat[(long long)bh * KCAT + KVLR + 2 * i]     = (x1 * c - x2 * s) * SCALE_F;
    qcat[(long long)bh * KCAT + KVLR + 2 * i + 1] = (x1 * s + x2 * c) * SCALE_F;
}

// ---------------- q_abs (FFMA), 256 blocks: (h, column half) ----------------
__global__ void __launch_bounds__(256) qabs_kernel(
    const float* __restrict__ q, const float* __restrict__ wkvb, float* __restrict__ qcat)
{
    int h = blockIdx.x >> 1;
    int c = (blockIdx.x & 1) * 256 + threadIdx.x;
    __shared__ __align__(16) float sq[DN][BATCH];
    int tid = threadIdx.x;
#pragma unroll
    for (int i = 0; i < 16; i++) {
        int idx = tid + i * 256;
        int d = idx >> 5, b = idx & 31;
        sq[d][b] = q[(long long)b * QDIM + h * QKD + d];
    }
    __syncthreads();
    ull acc[16];
#pragma unroll
    for (int i = 0; i < 16; i++) acc[i] = 0ull;
    const float* w = wkvb + (long long)h * 256 * KVLR + c;
#pragma unroll 4
    for (int d = 0; d < DN; d++) {
        ull w2 = dup2(w[(long long)d * KVLR]);
#pragma unroll
        for (int bp = 0; bp < 16; bp++) {
            ull qp = *(const ull*)&sq[d][bp * 2];
            acc[bp] = fma2(qp, w2, acc[bp]);
        }
    }
#pragma unroll
    for (int bp = 0; bp < 16; bp++) {
        float2 f = u2f(acc[bp]);
        qcat[((long long)(2 * bp + 0) * H + h) * KCAT + c] = f.x * SCALE_F;
        qcat[((long long)(2 * bp + 1) * H + h) * KCAT + c] = f.y * SCALE_F;
    }
}

// ---------------- KV row loader ----------------
__device__ __forceinline__ void load_kvrow16(float4* rb,
        const float* __restrict__ kvc, const float* __restrict__ pec,
        const float* __restrict__ kvnew, const float* __restrict__ penew,
        int b, int t, int spos, int k0)
{
    const float* src;
    if (k0 < KVLR)
        src = (t == spos) ? (kvnew + (long long)b * KVLR + k0)
                          : (kvc + ((long long)b * MAXS + t) * KVLR + k0);
    else
        src = (t == spos) ? (penew + (long long)b * DR + (k0 - KVLR))
                          : (pec + ((long long)b * MAXS + t) * DR + (k0 - KVLR));
#pragma unroll
    for (int j = 0; j < 4; j++) rb[j] = *(const float4*)(src + j * 4);
}

// =====================================================================
// scores + block-local softmax, double-buffered (unchanged from R9)
// =====================================================================
__global__ void __launch_bounds__(256) scores_sm(
    const float* __restrict__ qcat, const float* __restrict__ kvc, const float* __restrict__ pec,
    const float* __restrict__ kvnew, const float* __restrict__ penew,
    float* __restrict__ S, float2* __restrict__ mlv, const int* __restrict__ spos_p)
{
    const int b = blockIdx.z, spos = *spos_p;
    const int t0 = blockIdx.x * 256, h0 = blockIdx.y * 64;
    const float* A = qcat + ((long long)b * H + h0) * KCAT;
    float* C = S + ((long long)b * H + h0) * MAXS;

    __shared__ unsigned As[2][16][72];
    __shared__ unsigned Bs[2][16][264];
    __shared__ float red[64][4];

    const int tid = threadIdx.x, lane = tid & 31, wid = tid >> 5;
    const int gid = lane >> 2, tig = lane & 3;
    const int wh = (wid & 1) * 32, wt = (wid >> 1) * 64;
    const int wtq = wid >> 1;

    const int ah = tid >> 2, akq = (tid & 3) * 4;
    const int acol = ah ^ (8 * ((akq >> 2) & 3));
    const int bt = t0 + tid;

    float4 ra; float4 rb[4];
    ra = *(const float4*)(A + (long long)ah * KCAT + akq);
    load_kvrow16(rb, kvc, pec, kvnew, penew, b, bt, spos, 0);
    As[0][akq+0][acol] = f2tf(ra.x); As[0][akq+1][acol] = f2tf(ra.y);
    As[0][akq+2][acol] = f2tf(ra.z); As[0][akq+3][acol] = f2tf(ra.w);
#pragma unroll
    for (int j = 0; j < 4; j++) {
        Bs[0][j*4+0][tid] = f2tf(rb[j].x); Bs[0][j*4+1][tid] = f2tf(rb[j].y);
        Bs[0][j*4+2][tid] = f2tf(rb[j].z); Bs[0][j*4+3][tid] = f2tf(rb[j].w);
    }
    __syncthreads();

    float acc[2][8][4];
#pragma unroll
    for (int mi = 0; mi < 2; mi++)
#pragma unroll
        for (int nj = 0; nj < 8; nj++)
#pragma unroll
            for (int r = 0; r < 4; r++) acc[mi][nj][r] = 0.f;

    for (int it = 0; it < KCAT / 16; it++) {
        const int cur = it & 1, nxt = cur ^ 1;
        const bool more = (it + 1) < KCAT / 16;
        const int k1 = (it + 1) * 16;
        if (more) {
            ra = *(const float4*)(A + (long long)ah * KCAT + k1 + akq);
            load_kvrow16(rb, kvc, pec, kvnew, penew, b, bt, spos, k1);
        }
#pragma unroll
        for (int s = 0; s < 2; s++) {
            const int kk = s * 8;
            const int key0 = 8 * ((kk >> 2) & 3);
            const int key1 = 8 * (((kk >> 2) + 1) & 3);
            unsigned af[2][4];
#pragma unroll
            for (int mi = 0; mi < 2; mi++) {
                int r0 = wh + mi*16 + gid;
                af[mi][0] = As[cur][kk+tig  ][ r0    ^ key0];
                af[mi][1] = As[cur][kk+tig  ][(r0+8) ^ key0];
                af[mi][2] = As[cur][kk+tig+4][ r0    ^ key1];
                af[mi][3] = As[cur][kk+tig+4][(r0+8) ^ key1];
            }
            unsigned bf[8][2];
#pragma unroll
            for (int nj = 0; nj < 8; nj++) {
                bf[nj][0] = Bs[cur][kk+tig  ][wt + nj*8 + gid];
                bf[nj][1] = Bs[cur][kk+tig+4][wt + nj*8 + gid];
            }
#pragma unroll
            for (int mi = 0; mi < 2; mi++)
#pragma unroll
                for (int nj = 0; nj < 8; nj++)
                    mma8(acc[mi][nj], af[mi], bf[nj]);
        }
        if (more) {
            As[nxt][akq+0][acol] = f2tf(ra.x); As[nxt][akq+1][acol] = f2tf(ra.y);
            As[nxt][akq+2][acol] = f2tf(ra.z); As[nxt][akq+3][acol] = f2tf(ra.w);
#pragma unroll
            for (int j = 0; j < 4; j++) {
                Bs[nxt][j*4+0][tid] = f2tf(rb[j].x); Bs[nxt][j*4+1][tid] = f2tf(rb[j].y);
                Bs[nxt][j*4+2][tid] = f2tf(rb[j].z); Bs[nxt][j*4+3][tid] = f2tf(rb[j].w);
            }
        }
        __syncthreads();
    }

    // ---------------- block-local softmax epilogue ----------------
    float m_lo[2], m_hi[2];
#pragma unroll
    for (int mi = 0; mi < 2; mi++) {
        float a = -1e30f, c = -1e30f;
#pragma unroll
        for (int nj = 0; nj < 8; nj++) {
            int t = t0 + wt + nj*8 + 2*tig;
            float v0 = (t     <= spos) ? acc[mi][nj][0] : -1e30f;
            float v1 = (t + 1 <= spos) ? acc[mi][nj][1] : -1e30f;
            float v2 = (t     <= spos) ? acc[mi][nj][2] : -1e30f;
            float v3 = (t + 1 <= spos) ? acc[mi][nj][3] : -1e30f;
            a = fmaxf(a, fmaxf(v0, v1));
            c = fmaxf(c, fmaxf(v2, v3));
        }
        a = fmaxf(a, __shfl_xor_sync(0xffffffffu, a, 1));
        a = fmaxf(a, __shfl_xor_sync(0xffffffffu, a, 2));
        c = fmaxf(c, __shfl_xor_sync(0xffffffffu, c, 1));
        c = fmaxf(c, __shfl_xor_sync(0xffffffffu, c, 2));
        m_lo[mi] = a; m_hi[mi] = c;
    }
    if (tig == 0) {
#pragma unroll
        for (int mi = 0; mi < 2; mi++) {
            red[wh + mi*16 + gid    ][wtq] = m_lo[mi];
            red[wh + mi*16 + gid + 8][wtq] = m_hi[mi];
        }
    }
    __syncthreads();
#pragma unroll
    for (int mi = 0; mi < 2; mi++) {
        int r = wh + mi*16 + gid;
        m_lo[mi] = fmaxf(fmaxf(red[r][0],   red[r][1]),   fmaxf(red[r][2],   red[r][3]));
        m_hi[mi] = fmaxf(fmaxf(red[r+8][0], red[r+8][1]), fmaxf(red[r+8][2], red[r+8][3]));
    }
    __syncthreads();
    float s_lo[2] = {0.f, 0.f}, s_hi[2] = {0.f, 0.f};
#pragma unroll
    for (int mi = 0; mi < 2; mi++) {
#pragma unroll
        for (int nj = 0; nj < 8; nj++) {
            int t = t0 + wt + nj*8 + 2*tig;
            float e0 = (t     <= spos) ? __expf(acc[mi][nj][0] - m_lo[mi]) : 0.f;
            float e1 = (t + 1 <= spos) ? __expf(acc[mi][nj][1] - m_lo[mi]) : 0.f;
            float e2 = (t     <= spos) ? __expf(acc[mi][nj][2] - m_hi[mi]) : 0.f;
            float e3 = (t + 1 <= spos) ? __expf(acc[mi][nj][3] - m_hi[mi]) : 0.f;
            acc[mi][nj][0] = e0; acc[mi][nj][1] = e1;
            acc[mi][nj][2] = e2; acc[mi][nj][3] = e3;
            s_lo[mi] += e0 + e1; s_hi[mi] += e2 + e3;
        }
        s_lo[mi] += __shfl_xor_sync(0xffffffffu, s_lo[mi], 1);
        s_lo[mi] += __shfl_xor_sync(0xffffffffu, s_lo[mi], 2);
        s_hi[mi] += __shfl_xor_sync(0xffffffffu, s_hi[mi], 1);
        s_hi[mi] += __shfl_xor_sync(0xffffffffu, s_hi[mi], 2);
    }
    if (tig == 0) {
#pragma unroll
        for (int mi = 0; mi < 2; mi++) {
            red[wh + mi*16 + gid    ][wtq] = s_lo[mi];
            red[wh + mi*16 + gid + 8][wtq] = s_hi[mi];
        }
    }
    __syncthreads();
    if (wtq == 0 && tig == 0) {
#pragma unroll
        for (int mi = 0; mi < 2; mi++) {
            int r = wh + mi*16 + gid;
            float l0 = red[r][0]   + red[r][1]   + red[r][2]   + red[r][3];
            float l1 = red[r+8][0] + red[r+8][1] + red[r+8][2] + red[r+8][3];
            mlv[((long long)(b * H + h0 + r))     * NBLK + blockIdx.x] = make_float2(m_lo[mi], l0);
            mlv[((long long)(b * H + h0 + r + 8)) * NBLK + blockIdx.x] = make_float2(m_hi[mi], l1);
        }
    }

    // write P'
#pragma unroll
    for (int mi = 0; mi < 2; mi++)
#pragma unroll
        for (int nj = 0; nj < 8; nj++) {
            float* cp = C + (long long)(wh + mi*16 + gid) * MAXS + t0 + wt + nj*8 + 2*tig;
            *(float2*)cp            = make_float2(acc[mi][nj][0], acc[mi][nj][1]);
            *(float2*)(cp + 8*MAXS) = make_float2(acc[mi][nj][2], acc[mi][nj][3]);
        }
}

// ---------------- combine weights ----------------
__global__ void __launch_bounds__(256) wcomb_kernel(
    const float2* __restrict__ mlv, float* __restrict__ wv)
{
    int row = blockIdx.x * 256 + threadIdx.x;
    if (row >= BATCH * H) return;
    const float2* p = mlv + (long long)row * NBLK;
    float2 v[NBLK];
    float M = -1e30f;
#pragma unroll
    for (int i = 0; i < NBLK; i++) { v[i] = p[i]; M = fmaxf(M, v[i].x); }
    float L = 0.f;
#pragma unroll
    for (int i = 0; i < NBLK; i++) L += __expf(v[i].x - M) * v[i].y;
    float inv = 1.f / L;
#pragma unroll
    for (int i = 0; i < NBLK; i++)
        wv[(long long)row * NBLK + i] = __expf(v[i].x - M) * inv;
}

// =====================================================================
// olat: tile 64h x 256c, split-k over t (8), atomicAdd, double-buffered
// =====================================================================
__global__ void __launch_bounds__(256) olat_w(
    const float* __restrict__ P, const float* __restrict__ kvc,
    const float* __restrict__ kvnew, const float* __restrict__ wv,
    float* __restrict__ O, const int* __restrict__ spos_p)
{
    const int b = blockIdx.z, spos = *spos_p;
    const int c0 = blockIdx.x * 256;
    const int hb = blockIdx.y >> 3, ks = blockIdx.y & 7;
    const int h0 = hb * 64;
    const float* A = P + ((long long)b * H + h0) * MAXS;
    float* C = O + ((long long)b * H + h0) * KVLR;

    __shared__ unsigned As[2][16][72];
    __shared__ unsigned Bs[2][16][264];
    __shared__ float ws[64][16];

    const int tid = threadIdx.x, lane = tid & 31, wid = tid >> 5;
    const int gid = lane >> 2, tig = lane & 3;
    const int wh = (wid & 1) * 32, wc = (wid >> 1) * 64;

#pragma unroll
    for (int j = 0; j < 4; j++) {
        int idx = tid * 4 + j;
        int r = idx >> 4, blk = idx & 15;
        ws[r][blk] = wv[((long long)(b * H + h0 + r)) * NBLK + blk];
    }
    __syncthreads();

    const int ah = tid >> 2, akq = (tid & 3) * 4;
    const int acol = ah ^ (8 * ((akq >> 2) & 3));
    const int kbeg = ks * (MAXS/8);
    const int nIter = (MAXS/8) / 16;

    float4 ra; float4 rb[4];
    {
        float w0 = ws[ah][kbeg >> 8];
        ra = *(const float4*)(A + (long long)ah * MAXS + kbeg + akq);
        ra.x *= w0; ra.y *= w0; ra.z *= w0; ra.w *= w0;
    }
#pragma unroll
    for (int j = 0; j < 4; j++) {
        int idx = tid + j * 256;
        int r = idx >> 6, c4 = (idx & 63) * 4;
        int t = kbeg + r;
        const float* src = (t == spos) ? (kvnew + (long long)b * KVLR + c0 + c4)
                                       : (kvc + ((long long)b * MAXS + t) * KVLR + c0 + c4);
        rb[j] = *(const float4*)src;
    }
    As[0][akq+0][acol] = f2tf(ra.x); As[0][akq+1][acol] = f2tf(ra.y);
    As[0][akq+2][acol] = f2tf(ra.z); As[0][akq+3][acol] = f2tf(ra.w);
#pragma unroll
    for (int j = 0; j < 4; j++) {
        int idx = tid + j * 256;
        int r = idx >> 6, c4 = (idx & 63) * 4;
        uint4 u = make_uint4(f2tf(rb[j].x), f2tf(rb[j].y), f2tf(rb[j].z), f2tf(rb[j].w));
        *(uint4*)&Bs[0][r][c4] = u;
    }
    __syncthreads();

    float acc[2][8][4];
#pragma unroll
    for (int mi = 0; mi < 2; mi++)
#pragma unroll
        for (int nj = 0; nj < 8; nj++)
#pragma unroll
            for (int r = 0; r < 4; r++) acc[mi][nj][r] = 0.f;

    for (int it = 0; it < nIter; it++) {
        const int cur = it & 1, nxt = cur ^ 1;
        const bool more = (it + 1) < nIter;
        const int k1 = kbeg + (it + 1) * 16;
        if (more) {
            float w0 = ws[ah][k1 >> 8];
            ra = *(const float4*)(A + (long long)ah * MAXS + k1 + akq);
            ra.x *= w0; ra.y *= w0; ra.z *= w0; ra.w *= w0;
#pragma unroll
            for (int j = 0; j < 4; j++) {
                int idx = tid + j * 256;
                int r = idx >> 6, c4 = (idx & 63) * 4;
                int t = k1 + r;
                const float* src = (t == spos) ? (kvnew + (long long)b * KVLR + c0 + c4)
                                               : (kvc + ((long long)b * MAXS + t) * KVLR + c0 + c4);
                rb[j] = *(const float4*)src;
            }
        }
#pragma unroll
        for (int s = 0; s < 2; s++) {
            const int kk = s * 8;
            const int key0 = 8 * ((kk >> 2) & 3);
            const int key1 = 8 * (((kk >> 2) + 1) & 3);
            unsigned af[2][4];
#pragma unroll
            for (int mi = 0; mi < 2; mi++) {
                int r0 = wh + mi*16 + gid;
                af[mi][0] = As[cur][kk+tig  ][ r0    ^ key0];
                af[mi][1] = As[cur][kk+tig  ][(r0+8) ^ key0];
                af[mi][2] = As[cur][kk+tig+4][ r0    ^ key1];
                af[mi][3] = As[cur][kk+tig+4][(r0+8) ^ key1];
            }
            unsigned bf[8][2];
#pragma unroll
            for (int nj = 0; nj < 8; nj++) {
                bf[nj][0] = Bs[cur][kk+tig  ][wc + nj*8 + gid];
                bf[nj][1] = Bs[cur][kk+tig+4][wc + nj*8 + gid];
            }
#pragma unroll
            for (int mi = 0; mi < 2; mi++)
#pragma unroll
                for (int nj = 0; nj < 8; nj++)
                    mma8(acc[mi][nj], af[mi], bf[nj]);
        }
        if (more) {
            As[nxt][akq+0][acol] = f2tf(ra.x); As[nxt][akq+1][acol] = f2tf(ra.y);
            As[nxt][akq+2][acol] = f2tf(ra.z); As[nxt][akq+3][acol] = f2tf(ra.w);
#pragma unroll
            for (int j = 0; j < 4; j++) {
                int idx = tid + j * 256;
                int r = idx >> 6, c4 = (idx & 63) * 4;
                uint4 u = make_uint4(f2tf(rb[j].x), f2tf(rb[j].y), f2tf(rb[j].z), f2tf(rb[j].w));
                *(uint4*)&Bs[nxt][r][c4] = u;
            }
        }
        __syncthreads();
    }

#pragma unroll
    for (int mi = 0; mi < 2; mi++)
#pragma unroll
        for (int nj = 0; nj < 8; nj++) {
            float* cp = C + (long long)(wh + mi*16 + gid) * KVLR + c0 + wc + nj*8 + 2*tig;
            atomicAdd(cp,            acc[mi][nj][0]);
            atomicAdd(cp + 1,        acc[mi][nj][1]);
            atomicAdd(cp + 8*KVLR,   acc[mi][nj][2]);
            atomicAdd(cp + 8*KVLR+1, acc[mi][nj][3]);
        }
}

// =====================================================================
// FFMA split-K GEMV (kvfull, ohead)
// =====================================================================
template<int BN, int TN>
__global__ void __launch_bounds__(256) gemv_splitk(
    const float* __restrict__ A, const float* __restrict__ B, float* __restrict__ C,
    int N, int lda, int ldb, int ldc, int kChunk,
    long long aB, long long bB, long long cB)
{
    A += (long long)blockIdx.z * aB;
    B += (long long)blockIdx.z * bB;
    C += (long long)blockIdx.z * cB;
    const int n0 = blockIdx.x * BN;
    const int ks = blockIdx.y * kChunk;
    const int ke = ks + kChunk;

    __shared__ __align__(16) ull   As2[16][32];
    __shared__ __align__(16) float Bsf [16][BN];

    const int tid = threadIdx.x;
    const int tx = tid & 31, ty = tid >> 5;

    const bool aon = tid < 128;
    const int am = tid >> 2, akq = (tid & 3) << 2;
    constexpr int PER = BN / 64;
    const int bn  = tid % BN;
    const int bkq = (tid / BN) * PER;
    const bool bon = (n0 + bn) < N;

    float4 ra = make_float4(0,0,0,0);
    float4 rb[PER];
#pragma unroll
    for (int j = 0; j < PER; j++) rb[j] = make_float4(0,0,0,0);

    if (aon) ra = *(const float4*)(A + (long long)am * lda + ks + akq);
    if (bon) {
        const float* bp = B + (long long)(n0 + bn) * ldb + ks + bkq * 4;
#pragma unroll
        for (int j = 0; j < PER; j++) rb[j] = *(const float4*)(bp + j * 4);
    }
    if (aon) {
        As2[akq+0][am] = dup2(ra.x); As2[akq+1][am] = dup2(ra.y);
        As2[akq+2][am] = dup2(ra.z); As2[akq+3][am] = dup2(ra.w);
    }
#pragma unroll
    for (int j = 0; j < PER; j++) {
        Bsf[(bkq+j)*4+0][bn] = rb[j].x;
        Bsf[(bkq+j)*4+1][bn] = rb[j].y;
        Bsf[(bkq+j)*4+2][bn] = rb[j].z;
        Bsf[(bkq+j)*4+3][bn] = rb[j].w;
    }
    __syncthreads();

    ull acc[4][TN/2];
#pragma unroll
    for (int m = 0; m < 4; m++)
#pragma unroll
        for (int j = 0; j < TN/2; j++) acc[m][j] = 0ull;

    for (int k0 = ks; k0 < ke; k0 += 16) {
        const bool more = (k0 + 16) < ke;
        if (more) {
            if (aon) ra = *(const float4*)(A + (long long)am * lda + (k0+16) + akq);
            if (bon) {
                const float* bp = B + (long long)(n0 + bn) * ldb + (k0+16) + bkq * 4;
#pragma unroll
                for (int j = 0; j < PER; j++) rb[j] = *(const float4*)(bp + j * 4);
            }
        }
#pragma unroll
        for (int kk = 0; kk < 16; kk++) {
            ulonglong2 a01 = *(const ulonglong2*)&As2[kk][ty*4];
            ulonglong2 a23 = *(const ulonglong2*)&As2[kk][ty*4+2];
            ull a[4] = {a01.x, a01.y, a23.x, a23.y};
            ull bq[TN/2];
            if constexpr (TN == 8) {
                ulonglong2 b0 = *(const ulonglong2*)&Bsf[kk][tx*8];
                ulonglong2 b1 = *(const ulonglong2*)&Bsf[kk][tx*8+4];
                bq[0]=b0.x; bq[1]=b0.y; bq[2]=b1.x; bq[3]=b1.y;
            } else {
                ulonglong2 b0 = *(const ulonglong2*)&Bsf[kk][tx*4];
                bq[0]=b0.x; bq[1]=b0.y;
            }
#pragma unroll
            for (int m = 0; m < 4; m++)
#pragma unroll
                for (int j = 0; j < TN/2; j++)
                    acc[m][j] = fma2(a[m], bq[j], acc[m][j]);
        }
        __syncthreads();
        if (more) {
            if (aon) {
                As2[akq+0][am] = dup2(ra.x); As2[akq+1][am] = dup2(ra.y);
                As2[akq+2][am] = dup2(ra.z); As2[akq+3][am] = dup2(ra.w);
            }
#pragma unroll
            for (int j = 0; j < PER; j++) {
                Bsf[(bkq+j)*4+0][bn] = rb[j].x;
                Bsf[(bkq+j)*4+1][bn] = rb[j].y;
                Bsf[(bkq+j)*4+2][bn] = rb[j].z;
                Bsf[(bkq+j)*4+3][bn] = rb[j].w;
            }
        }
        __syncthreads();
    }

    const int nb = n0 + tx * TN;
#pragma unroll
    for (int m = 0; m < 4; m++) {
        float* cp = C + (long long)(ty*4+m) * ldc + nb;
#pragma unroll
        for (int j = 0; j < TN/2; j++) {
            float2 f = u2f(acc[m][j]);
            if (nb + 2*j     < N) atomicAdd(cp + 2*j,     f.x);
            if (nb + 2*j + 1 < N) atomicAdd(cp + 2*j + 1, f.y);
        }
    }
}

// ---------------- launch ----------------
extern "C" void kernel_launch(void* const* d_in, const int* in_sizes, int n_in,
                              void* d_out, int out_size)
{
    const float* x        = (const float*)d_in[0];
    const float* fc       = (const float*)d_in[1];
    const float* fs       = (const float*)d_in[2];
    const float* kvc      = (const float*)d_in[3];
    const float* pec      = (const float*)d_in[4];
    const float* wq_a     = (const float*)d_in[5];
    const float* q_norm_w = (const float*)d_in[6];
    const float* wq_b     = (const float*)d_in[7];
    const float* wkv_a    = (const float*)d_in[8];
    const float* kv_norm  = (const float*)d_in[9];
    const float* wkv_b    = (const float*)d_in[10];
    const float* wo       = (const float*)d_in[11];
    const int*   spos     = (const int*)d_in[12];
    float*       out      = (float*)d_out;

    float *qlat, *kvfull, *kvnew, *penew, *q, *qcat, *scores, *ml, *wv, *olat, *ohead;
    cudaGetSymbolAddress((void**)&qlat,   g_qlat);
    cudaGetSymbolAddress((void**)&kvfull, g_kvfull);
    cudaGetSymbolAddress((void**)&kvnew,  g_kvnew);
    cudaGetSymbolAddress((void**)&penew,  g_penew);
    cudaGetSymbolAddress((void**)&q,      g_q);
    cudaGetSymbolAddress((void**)&qcat,   g_qcat);
    cudaGetSymbolAddress((void**)&scores, g_scores);
    cudaGetSymbolAddress((void**)&ml,     g_ml);
    cudaGetSymbolAddress((void**)&wv,     g_w);
    cudaGetSymbolAddress((void**)&olat,   g_olat);
    cudaGetSymbolAddress((void**)&ohead,  g_ohead);

    cudaMemsetAsync(qlat,   0, (size_t)BATCH * QLR  * 4);
    cudaMemsetAsync(kvfull, 0, (size_t)BATCH * KCAT * 4);
    cudaMemsetAsync(q,      0, (size_t)BATCH * QDIM * 4);
    cudaMemsetAsync(olat,   0, (size_t)BATCH * H * KVLR * 4);
    cudaMemsetAsync(ohead,  0, (size_t)BATCH * ODIM * 4);
    cudaMemsetAsync(out,    0, (size_t)out_size * 4);

    dim3 blk(256);

    // q_lat = x @ wq_a^T   (N=1536, K=7168): 192 blocks
    gemv_mma<<<dim3(6,32,1), blk>>>(x, wq_a, qlat, DIM, DIM, QLR, 224);
    // kv_full = x @ wkv_a^T (N=576, K=7168): 192 blocks
    gemv_splitk<256,8><<<dim3(3,64,1), blk>>>(x, wkv_a, kvfull, KCAT, DIM, DIM, KCAT, 112, 0,0,0);
    // merged rmsnorm(qlat) + kvprep
    norms_kernel<<<64, 256>>>(qlat, q_norm_w, kvfull, kv_norm, fc, fs, kvnew, penew);
    // q = q_lat @ wq_b^T   (N=24576, K=1536): 96 x 12 = 1152 blocks
    gemv_mma<<<dim3(96,12,1), blk>>>(qlat, wq_b, q, QLR, QLR, QDIM, 128);
    qrope_kernel<<<512, 256>>>(q, fc, fs, qcat);
    // q_abs: 256 blocks (h x column-half)
    qabs_kernel<<<256, 256>>>(q, wkv_b, qcat);
    // scores + block-local softmax: 1024 blocks
    scores_sm<<<dim3(MAXS/256, H/64, BATCH), blk>>>(
        qcat, kvc, pec, kvnew, penew, scores, (float2*)ml, spos);
    // block weights
    wcomb_kernel<<<(BATCH*H + 255)/256, 256>>>((const float2*)ml, wv);
    // weighted olat: 1024 blocks
    olat_w<<<dim3(KVLR/256, 16, BATCH), blk>>>(scores, kvc, kvnew, wv, olat, spos);
    // ohead per head, 2 k-splits: 256 blocks
    gemv_splitk<128,4><<<dim3(1,2,H), blk>>>(olat, wkv_b + 128*KVLR, ohead,
                                             DV, H*KVLR, KVLR, ODIM, 256,
                                             (long long)KVLR, (long long)256*KVLR, (long long)DV);
    // out = ohead @ wo^T   (N=7168, K=16384): 28 x 32 = 896 blocks
    gemv_mma<<<dim3(28,32,1), blk>>>(ohead, wo, out, ODIM, ODIM, DIM, 512);
}